// round 1
// baseline (speedup 1.0000x reference)
#include <cuda_runtime.h>

#define BB 16
#define CC 64
#define NN 4096   // H*W
#define MM 1024   // N/4

// Scratch (allocation-free: __device__ globals)
__device__ __align__(16) float g_theta[BB * NN * 8];          // [b][q][8]
__device__ __align__(16) float g_phi[BB * MM * 8];            // [b][m][8]
__device__ __align__(16) float g_gT[BB * MM * 32];            // [b][m][32]
__device__ __align__(16) float g_oT[(size_t)BB * NN * 32];    // [b][q][32]

typedef unsigned long long ull;

__device__ __forceinline__ ull fma2(ull a, ull b, ull c) {
    ull d;
    asm("fma.rn.f32x2 %0, %1, %2, %3;" : "=l"(d) : "l"(a), "l"(b), "l"(c));
    return d;
}
__device__ __forceinline__ ull mul2(ull a, ull b) {
    ull d;
    asm("mul.rn.f32x2 %0, %1, %2;" : "=l"(d) : "l"(a), "l"(b));
    return d;
}
__device__ __forceinline__ ull pack2(float lo, float hi) {
    ull d;
    asm("mov.b64 %0, {%1, %2};" : "=l"(d) : "f"(lo), "f"(hi));
    return d;
}
__device__ __forceinline__ void unpack2(ull v, float& lo, float& hi) {
    asm("mov.b64 {%0, %1}, %2;" : "=f"(lo), "=f"(hi) : "l"(v));
}

// ---------------------------------------------------------------------------
// Kernel A: theta = W_theta @ x + b_theta, stored [b][q][8]
// ---------------------------------------------------------------------------
__global__ void __launch_bounds__(256) theta_kernel(
        const float* __restrict__ x,
        const float* __restrict__ Wt,
        const float* __restrict__ bt) {
    __shared__ __align__(16) float WT[64 * 8];   // [c][k]
    __shared__ float b_s[8];
    int tid = threadIdx.x;
    for (int i = tid; i < 512; i += 256) {
        int k = i & 7, c = i >> 3;
        WT[i] = Wt[k * 64 + c];
    }
    if (tid < 8) b_s[tid] = bt[tid];
    __syncthreads();

    int p = blockIdx.x * 256 + tid;
    int b = p >> 12;
    int q = p & 4095;
    const float* xp = x + (size_t)b * CC * NN + q;

    ull acc[4] = {0ull, 0ull, 0ull, 0ull};
    #pragma unroll 8
    for (int c = 0; c < 64; c++) {
        float xv = xp[(size_t)c * NN];
        ull v2 = pack2(xv, xv);
        const ulonglong2* wr = (const ulonglong2*)(WT + c * 8);
        ulonglong2 w0 = wr[0];
        ulonglong2 w1 = wr[1];
        acc[0] = fma2(v2, w0.x, acc[0]);
        acc[1] = fma2(v2, w0.y, acc[1]);
        acc[2] = fma2(v2, w1.x, acc[2]);
        acc[3] = fma2(v2, w1.y, acc[3]);
    }
    float o0, o1, o2, o3, o4, o5, o6, o7;
    unpack2(acc[0], o0, o1);
    unpack2(acc[1], o2, o3);
    unpack2(acc[2], o4, o5);
    unpack2(acc[3], o6, o7);
    float4* op = (float4*)(g_theta + (size_t)p * 8);
    op[0] = make_float4(o0 + b_s[0], o1 + b_s[1], o2 + b_s[2], o3 + b_s[3]);
    op[1] = make_float4(o4 + b_s[4], o5 + b_s[5], o6 + b_s[6], o7 + b_s[7]);
}

// ---------------------------------------------------------------------------
// Kernel B: phi = maxpool2(W_phi @ x) + b_phi -> [b][m][8]
//           g   = maxpool2(W_g   @ x) + b_g   -> [b][m][32] (channel-last)
// (bias is per-channel constant: max(y)+b == max(y+b), so add after pooling)
// ---------------------------------------------------------------------------
__global__ void __launch_bounds__(128) pool_kernel(
        const float* __restrict__ x,
        const float* __restrict__ Wp, const float* __restrict__ bp,
        const float* __restrict__ Wg, const float* __restrict__ bg) {
    __shared__ __align__(16) float WT[64 * 40];  // [c][o]; o<8: phi, o>=8: g
    __shared__ float bias_s[40];
    int tid = threadIdx.x;
    for (int i = tid; i < 2560; i += 128) {
        int o = i % 40, c = i / 40;
        WT[i] = (o < 8) ? Wp[o * 64 + c] : Wg[(o - 8) * 64 + c];
    }
    if (tid < 40) bias_s[tid] = (tid < 8) ? bp[tid] : bg[tid - 8];
    __syncthreads();

    int p = blockIdx.x * 128 + tid;
    int b = p >> 10;
    int m = p & 1023;
    int hp = m >> 5, wp = m & 31;
    const float* xb = x + (size_t)b * CC * NN;

    float mx[40];
    #pragma unroll
    for (int o = 0; o < 40; o++) mx[o] = -3.4e38f;

    #pragma unroll
    for (int dy = 0; dy < 2; dy++) {
        #pragma unroll
        for (int dx = 0; dx < 2; dx++) {
            int q = (2 * hp + dy) * 64 + 2 * wp + dx;
            ull y[20];
            #pragma unroll
            for (int j = 0; j < 20; j++) y[j] = 0ull;
            for (int c = 0; c < 64; c++) {
                float xv = xb[(size_t)c * NN + q];
                ull v2 = pack2(xv, xv);
                const ulonglong2* wr = (const ulonglong2*)(WT + c * 40);
                #pragma unroll
                for (int j = 0; j < 10; j++) {
                    ulonglong2 wv = wr[j];
                    y[2 * j]     = fma2(v2, wv.x, y[2 * j]);
                    y[2 * j + 1] = fma2(v2, wv.y, y[2 * j + 1]);
                }
            }
            #pragma unroll
            for (int j = 0; j < 20; j++) {
                float lo, hi;
                unpack2(y[j], lo, hi);
                mx[2 * j]     = fmaxf(mx[2 * j], lo);
                mx[2 * j + 1] = fmaxf(mx[2 * j + 1], hi);
            }
        }
    }
    float* php = g_phi + (size_t)p * 8;
    #pragma unroll
    for (int k = 0; k < 8; k++) php[k] = mx[k] + bias_s[k];
    float* gp = g_gT + (size_t)p * 32;
    #pragma unroll
    for (int j = 0; j < 32; j++) gp[j] = mx[8 + j] + bias_s[8 + j];
}

// ---------------------------------------------------------------------------
// Kernel C: fused attention. One thread = one query.
//   logits[m] = theta_q . phi_m  (8-dim);  beta = softmax over m (no max
//   subtraction needed: logits bounded far below fp32 exp overflow);
//   o[c] = sum_m beta[m] * g[c][m], accumulated flash-style.
// phi (32KB) + gT (128KB) of one batch live in 160KB dynamic smem; the m loop
// is warp-uniform so all LDS are conflict-free broadcasts.
// ---------------------------------------------------------------------------
__global__ void __launch_bounds__(512, 1) attn_kernel() {
    extern __shared__ __align__(16) float sm[];
    float* phi_s = sm;           // 8192 floats
    float* g_s   = sm + 8192;    // 32768 floats
    int b = blockIdx.x >> 3;
    int chunk = blockIdx.x & 7;
    int tid = threadIdx.x;

    {
        const float4* src = (const float4*)(g_phi + (size_t)b * MM * 8);
        float4* dst = (float4*)phi_s;
        for (int i = tid; i < 2048; i += 512) dst[i] = src[i];
        const float4* src2 = (const float4*)(g_gT + (size_t)b * MM * 32);
        float4* dst2 = (float4*)g_s;
        for (int i = tid; i < 8192; i += 512) dst2[i] = src2[i];
    }
    __syncthreads();

    int q = chunk * 512 + tid;
    const ulonglong2* th = (const ulonglong2*)(g_theta + ((size_t)b * NN + q) * 8);
    ulonglong2 tA = th[0];
    ulonglong2 tB = th[1];

    ull acc[16];
    #pragma unroll
    for (int j = 0; j < 16; j++) acc[j] = 0ull;
    float denom = 0.0f;

    #pragma unroll 2
    for (int m = 0; m < MM; m++) {
        const ulonglong2* pr = (const ulonglong2*)(phi_s + m * 8);
        ulonglong2 pA = pr[0];
        ulonglong2 pB = pr[1];
        ull s = mul2(tA.x, pA.x);
        s = fma2(tA.y, pA.y, s);
        s = fma2(tB.x, pB.x, s);
        s = fma2(tB.y, pB.y, s);
        float lo, hi;
        unpack2(s, lo, hi);
        float e = __expf(lo + hi);
        denom += e;
        ull e2 = pack2(e, e);
        const ulonglong2* gr = (const ulonglong2*)(g_s + m * 32);
        #pragma unroll
        for (int j = 0; j < 8; j++) {
            ulonglong2 gv = gr[j];
            acc[2 * j]     = fma2(e2, gv.x, acc[2 * j]);
            acc[2 * j + 1] = fma2(e2, gv.y, acc[2 * j + 1]);
        }
    }

    float inv = 1.0f / denom;
    float4* op = (float4*)(g_oT + ((size_t)b * NN + q) * 32);
    #pragma unroll
    for (int j = 0; j < 8; j++) {
        float a0, a1, a2v, a3;
        unpack2(acc[2 * j], a0, a1);
        unpack2(acc[2 * j + 1], a2v, a3);
        op[j] = make_float4(a0 * inv, a1 * inv, a2v * inv, a3 * inv);
    }
}

// ---------------------------------------------------------------------------
// Kernel D: out = gamma * (W_o @ o + b_o) + inputs
// ---------------------------------------------------------------------------
__global__ void __launch_bounds__(128) out_kernel(
        const float* __restrict__ x,
        const float* __restrict__ Wo, const float* __restrict__ bo,
        const float* __restrict__ gam,
        float* __restrict__ out) {
    __shared__ __align__(16) float WT[32 * 64];   // [ci][co]
    __shared__ float b_s[64];
    int tid = threadIdx.x;
    for (int i = tid; i < 2048; i += 128) {
        int co = i >> 5, ci = i & 31;
        WT[ci * 64 + co] = Wo[i];
    }
    if (tid < 64) b_s[tid] = bo[tid];
    __syncthreads();

    int p = blockIdx.x * 128 + tid;
    int b = p >> 12;
    int q = p & 4095;

    float ov[32];
    {
        const float4* ov4 = (const float4*)(g_oT + (size_t)p * 32);
        #pragma unroll
        for (int j = 0; j < 8; j++) {
            float4 t = ov4[j];
            ov[4 * j]     = t.x;
            ov[4 * j + 1] = t.y;
            ov[4 * j + 2] = t.z;
            ov[4 * j + 3] = t.w;
        }
    }

    ull acc[32];
    #pragma unroll
    for (int j = 0; j < 32; j++) acc[j] = 0ull;

    #pragma unroll 4
    for (int ci = 0; ci < 32; ci++) {
        ull v2 = pack2(ov[ci], ov[ci]);
        const ulonglong2* wr = (const ulonglong2*)(WT + ci * 64);
        #pragma unroll
        for (int j = 0; j < 16; j++) {
            ulonglong2 wv = wr[j];
            acc[2 * j]     = fma2(v2, wv.x, acc[2 * j]);
            acc[2 * j + 1] = fma2(v2, wv.y, acc[2 * j + 1]);
        }
    }

    float gma = gam[0];
    const float* xp = x + (size_t)b * CC * NN + q;
    float* outp = out + (size_t)b * CC * NN + q;
    #pragma unroll
    for (int j = 0; j < 32; j++) {
        float lo, hi;
        unpack2(acc[j], lo, hi);
        int co = 2 * j;
        outp[(size_t)co * NN]       = gma * (lo + b_s[co])     + xp[(size_t)co * NN];
        outp[(size_t)(co + 1) * NN] = gma * (hi + b_s[co + 1]) + xp[(size_t)(co + 1) * NN];
    }
}

// ---------------------------------------------------------------------------
extern "C" void kernel_launch(void* const* d_in, const int* in_sizes, int n_in,
                              void* d_out, int out_size) {
    const float* x   = (const float*)d_in[0];
    const float* Wt  = (const float*)d_in[1];
    const float* bt  = (const float*)d_in[2];
    const float* Wp  = (const float*)d_in[3];
    const float* bp  = (const float*)d_in[4];
    const float* Wg  = (const float*)d_in[5];
    const float* bg  = (const float*)d_in[6];
    const float* Wo  = (const float*)d_in[7];
    const float* bo  = (const float*)d_in[8];
    const float* gam = (const float*)d_in[9];
    float* out = (float*)d_out;

    theta_kernel<<<BB * NN / 256, 256>>>(x, Wt, bt);
    pool_kernel<<<BB * MM / 128, 128>>>(x, Wp, bp, Wg, bg);

    const int SMEM_C = (8192 + 32768) * (int)sizeof(float);   // 160 KB
    cudaFuncSetAttribute(attn_kernel,
                         cudaFuncAttributeMaxDynamicSharedMemorySize, SMEM_C);
    attn_kernel<<<BB * 8, 512, SMEM_C>>>();

    out_kernel<<<BB * NN / 128, 128>>>(x, Wo, bo, gam, out);
}

// round 2
// speedup vs baseline: 1.0019x; 1.0019x over previous
#include <cuda_runtime.h>

#define BB 16
#define CC 64
#define NN 4096   // H*W
#define MM 1024   // N/4

// Scratch (allocation-free: __device__ globals)
__device__ __align__(16) float g_theta[BB * NN * 8];          // [b][q][8]
__device__ __align__(16) float g_phi[BB * MM * 8];            // [b][m][8]
__device__ __align__(16) float g_gT[BB * MM * 32];            // [b][m][32]
__device__ __align__(16) float g_oT[(size_t)BB * NN * 32];    // [b][q][32]

typedef unsigned long long ull;

__device__ __forceinline__ ull fma2(ull a, ull b, ull c) {
    ull d;
    asm("fma.rn.f32x2 %0, %1, %2, %3;" : "=l"(d) : "l"(a), "l"(b), "l"(c));
    return d;
}
__device__ __forceinline__ ull mul2(ull a, ull b) {
    ull d;
    asm("mul.rn.f32x2 %0, %1, %2;" : "=l"(d) : "l"(a), "l"(b));
    return d;
}
__device__ __forceinline__ ull pack2(float lo, float hi) {
    ull d;
    asm("mov.b64 %0, {%1, %2};" : "=l"(d) : "f"(lo), "f"(hi));
    return d;
}
__device__ __forceinline__ void unpack2(ull v, float& lo, float& hi) {
    asm("mov.b64 {%0, %1}, %2;" : "=f"(lo), "=f"(hi) : "l"(v));
}

// ---------------------------------------------------------------------------
// Kernel A: theta = W_theta @ x + b_theta, stored [b][q][8]
// ---------------------------------------------------------------------------
__global__ void __launch_bounds__(256) theta_kernel(
        const float* __restrict__ x,
        const float* __restrict__ Wt,
        const float* __restrict__ bt) {
    __shared__ __align__(16) float WT[64 * 8];   // [c][k]
    __shared__ float b_s[8];
    int tid = threadIdx.x;
    for (int i = tid; i < 512; i += 256) {
        int k = i & 7, c = i >> 3;
        WT[i] = Wt[k * 64 + c];
    }
    if (tid < 8) b_s[tid] = bt[tid];
    __syncthreads();

    int p = blockIdx.x * 256 + tid;
    int b = p >> 12;
    int q = p & 4095;
    const float* xp = x + (size_t)b * CC * NN + q;

    ull acc[4] = {0ull, 0ull, 0ull, 0ull};
    #pragma unroll 8
    for (int c = 0; c < 64; c++) {
        float xv = xp[(size_t)c * NN];
        ull v2 = pack2(xv, xv);
        const ulonglong2* wr = (const ulonglong2*)(WT + c * 8);
        ulonglong2 w0 = wr[0];
        ulonglong2 w1 = wr[1];
        acc[0] = fma2(v2, w0.x, acc[0]);
        acc[1] = fma2(v2, w0.y, acc[1]);
        acc[2] = fma2(v2, w1.x, acc[2]);
        acc[3] = fma2(v2, w1.y, acc[3]);
    }
    float o0, o1, o2, o3, o4, o5, o6, o7;
    unpack2(acc[0], o0, o1);
    unpack2(acc[1], o2, o3);
    unpack2(acc[2], o4, o5);
    unpack2(acc[3], o6, o7);
    float4* op = (float4*)(g_theta + (size_t)p * 8);
    op[0] = make_float4(o0 + b_s[0], o1 + b_s[1], o2 + b_s[2], o3 + b_s[3]);
    op[1] = make_float4(o4 + b_s[4], o5 + b_s[5], o6 + b_s[6], o7 + b_s[7]);
}

// ---------------------------------------------------------------------------
// Kernel B: phi = maxpool2(W_phi @ x) + b_phi -> [b][m][8]
//           g   = maxpool2(W_g   @ x) + b_g   -> [b][m][32] (channel-last)
// (bias is per-channel constant: max(y)+b == max(y+b), so add after pooling)
// ---------------------------------------------------------------------------
__global__ void __launch_bounds__(128) pool_kernel(
        const float* __restrict__ x,
        const float* __restrict__ Wp, const float* __restrict__ bp,
        const float* __restrict__ Wg, const float* __restrict__ bg) {
    __shared__ __align__(16) float WT[64 * 40];  // [c][o]; o<8: phi, o>=8: g
    __shared__ float bias_s[40];
    int tid = threadIdx.x;
    for (int i = tid; i < 2560; i += 128) {
        int o = i % 40, c = i / 40;
        WT[i] = (o < 8) ? Wp[o * 64 + c] : Wg[(o - 8) * 64 + c];
    }
    if (tid < 40) bias_s[tid] = (tid < 8) ? bp[tid] : bg[tid - 8];
    __syncthreads();

    int p = blockIdx.x * 128 + tid;
    int b = p >> 10;
    int m = p & 1023;
    int hp = m >> 5, wp = m & 31;
    const float* xb = x + (size_t)b * CC * NN;

    float mx[40];
    #pragma unroll
    for (int o = 0; o < 40; o++) mx[o] = -3.4e38f;

    #pragma unroll
    for (int dy = 0; dy < 2; dy++) {
        #pragma unroll
        for (int dx = 0; dx < 2; dx++) {
            int q = (2 * hp + dy) * 64 + 2 * wp + dx;
            ull y[20];
            #pragma unroll
            for (int j = 0; j < 20; j++) y[j] = 0ull;
            for (int c = 0; c < 64; c++) {
                float xv = xb[(size_t)c * NN + q];
                ull v2 = pack2(xv, xv);
                const ulonglong2* wr = (const ulonglong2*)(WT + c * 40);
                #pragma unroll
                for (int j = 0; j < 10; j++) {
                    ulonglong2 wv = wr[j];
                    y[2 * j]     = fma2(v2, wv.x, y[2 * j]);
                    y[2 * j + 1] = fma2(v2, wv.y, y[2 * j + 1]);
                }
            }
            #pragma unroll
            for (int j = 0; j < 20; j++) {
                float lo, hi;
                unpack2(y[j], lo, hi);
                mx[2 * j]     = fmaxf(mx[2 * j], lo);
                mx[2 * j + 1] = fmaxf(mx[2 * j + 1], hi);
            }
        }
    }
    float* php = g_phi + (size_t)p * 8;
    #pragma unroll
    for (int k = 0; k < 8; k++) php[k] = mx[k] + bias_s[k];
    float* gp = g_gT + (size_t)p * 32;
    #pragma unroll
    for (int j = 0; j < 32; j++) gp[j] = mx[8 + j] + bias_s[8 + j];
}

// ---------------------------------------------------------------------------
// Kernel C: fused attention. One thread = one query.
//   logits[m] = theta_q . phi_m  (8-dim);  beta = softmax over m (no max
//   subtraction needed: logits bounded far below fp32 exp overflow);
//   o[c] = sum_m beta[m] * g[c][m], accumulated flash-style.
// phi (32KB) + gT (128KB) of one batch live in 160KB dynamic smem; the m loop
// is warp-uniform so all LDS are conflict-free broadcasts.
// ---------------------------------------------------------------------------
__global__ void __launch_bounds__(512, 1) attn_kernel() {
    extern __shared__ __align__(16) float sm[];
    float* phi_s = sm;           // 8192 floats
    float* g_s   = sm + 8192;    // 32768 floats
    int b = blockIdx.x >> 3;
    int chunk = blockIdx.x & 7;
    int tid = threadIdx.x;

    {
        const float4* src = (const float4*)(g_phi + (size_t)b * MM * 8);
        float4* dst = (float4*)phi_s;
        for (int i = tid; i < 2048; i += 512) dst[i] = src[i];
        const float4* src2 = (const float4*)(g_gT + (size_t)b * MM * 32);
        float4* dst2 = (float4*)g_s;
        for (int i = tid; i < 8192; i += 512) dst2[i] = src2[i];
    }
    __syncthreads();

    int q = chunk * 512 + tid;
    const ulonglong2* th = (const ulonglong2*)(g_theta + ((size_t)b * NN + q) * 8);
    ulonglong2 tA = th[0];
    ulonglong2 tB = th[1];

    ull acc[16];
    #pragma unroll
    for (int j = 0; j < 16; j++) acc[j] = 0ull;
    float denom = 0.0f;

    #pragma unroll 2
    for (int m = 0; m < MM; m++) {
        const ulonglong2* pr = (const ulonglong2*)(phi_s + m * 8);
        ulonglong2 pA = pr[0];
        ulonglong2 pB = pr[1];
        ull s = mul2(tA.x, pA.x);
        s = fma2(tA.y, pA.y, s);
        s = fma2(tB.x, pB.x, s);
        s = fma2(tB.y, pB.y, s);
        float lo, hi;
        unpack2(s, lo, hi);
        float e = __expf(lo + hi);
        denom += e;
        ull e2 = pack2(e, e);
        const ulonglong2* gr = (const ulonglong2*)(g_s + m * 32);
        #pragma unroll
        for (int j = 0; j < 8; j++) {
            ulonglong2 gv = gr[j];
            acc[2 * j]     = fma2(e2, gv.x, acc[2 * j]);
            acc[2 * j + 1] = fma2(e2, gv.y, acc[2 * j + 1]);
        }
    }

    float inv = 1.0f / denom;
    float4* op = (float4*)(g_oT + ((size_t)b * NN + q) * 32);
    #pragma unroll
    for (int j = 0; j < 8; j++) {
        float a0, a1, a2v, a3;
        unpack2(acc[2 * j], a0, a1);
        unpack2(acc[2 * j + 1], a2v, a3);
        op[j] = make_float4(a0 * inv, a1 * inv, a2v * inv, a3 * inv);
    }
}

// ---------------------------------------------------------------------------
// Kernel D: out = gamma * (W_o @ o + b_o) + inputs
// ---------------------------------------------------------------------------
__global__ void __launch_bounds__(128) out_kernel(
        const float* __restrict__ x,
        const float* __restrict__ Wo, const float* __restrict__ bo,
        const float* __restrict__ gam,
        float* __restrict__ out) {
    __shared__ __align__(16) float WT[32 * 64];   // [ci][co]
    __shared__ float b_s[64];
    int tid = threadIdx.x;
    for (int i = tid; i < 2048; i += 128) {
        int co = i >> 5, ci = i & 31;
        WT[ci * 64 + co] = Wo[i];
    }
    if (tid < 64) b_s[tid] = bo[tid];
    __syncthreads();

    int p = blockIdx.x * 128 + tid;
    int b = p >> 12;
    int q = p & 4095;

    float ov[32];
    {
        const float4* ov4 = (const float4*)(g_oT + (size_t)p * 32);
        #pragma unroll
        for (int j = 0; j < 8; j++) {
            float4 t = ov4[j];
            ov[4 * j]     = t.x;
            ov[4 * j + 1] = t.y;
            ov[4 * j + 2] = t.z;
            ov[4 * j + 3] = t.w;
        }
    }

    ull acc[32];
    #pragma unroll
    for (int j = 0; j < 32; j++) acc[j] = 0ull;

    #pragma unroll 4
    for (int ci = 0; ci < 32; ci++) {
        ull v2 = pack2(ov[ci], ov[ci]);
        const ulonglong2* wr = (const ulonglong2*)(WT + ci * 64);
        #pragma unroll
        for (int j = 0; j < 16; j++) {
            ulonglong2 wv = wr[j];
            acc[2 * j]     = fma2(v2, wv.x, acc[2 * j]);
            acc[2 * j + 1] = fma2(v2, wv.y, acc[2 * j + 1]);
        }
    }

    float gma = gam[0];
    const float* xp = x + (size_t)b * CC * NN + q;
    float* outp = out + (size_t)b * CC * NN + q;
    #pragma unroll
    for (int j = 0; j < 32; j++) {
        float lo, hi;
        unpack2(acc[j], lo, hi);
        int co = 2 * j;
        outp[(size_t)co * NN]       = gma * (lo + b_s[co])     + xp[(size_t)co * NN];
        outp[(size_t)(co + 1) * NN] = gma * (hi + b_s[co + 1]) + xp[(size_t)(co + 1) * NN];
    }
}

// ---------------------------------------------------------------------------
extern "C" void kernel_launch(void* const* d_in, const int* in_sizes, int n_in,
                              void* d_out, int out_size) {
    const float* x   = (const float*)d_in[0];
    const float* Wt  = (const float*)d_in[1];
    const float* bt  = (const float*)d_in[2];
    const float* Wp  = (const float*)d_in[3];
    const float* bp  = (const float*)d_in[4];
    const float* Wg  = (const float*)d_in[5];
    const float* bg  = (const float*)d_in[6];
    const float* Wo  = (const float*)d_in[7];
    const float* bo  = (const float*)d_in[8];
    const float* gam = (const float*)d_in[9];
    float* out = (float*)d_out;

    theta_kernel<<<BB * NN / 256, 256>>>(x, Wt, bt);
    pool_kernel<<<BB * MM / 128, 128>>>(x, Wp, bp, Wg, bg);

    const int SMEM_C = (8192 + 32768) * (int)sizeof(float);   // 160 KB
    cudaFuncSetAttribute(attn_kernel,
                         cudaFuncAttributeMaxDynamicSharedMemorySize, SMEM_C);
    attn_kernel<<<BB * 8, 512, SMEM_C>>>();

    out_kernel<<<BB * NN / 128, 128>>>(x, Wo, bo, gam, out);
}

// round 9
// speedup vs baseline: 1.9476x; 1.9439x over previous
#include <cuda_runtime.h>
#include <cuda_bf16.h>
#include <cstdint>

#define BB 16
#define CC 64
#define NN 4096   // H*W
#define MM 1024   // N/4

// Scratch (allocation-free: __device__ globals)
__device__ __align__(16) float g_theta[BB * NN * 8];              // [b][q][8]
__device__ __align__(16) float g_phi[BB * MM * 8];                // [b][m][8]
__device__ __align__(16) __nv_bfloat16 g_gbf[BB * 32 * MM];       // [b][c'][m] bf16
__device__ __align__(16) float g_oT[(size_t)BB * NN * 32];        // [b][q][32]

typedef unsigned long long ull;

__device__ __forceinline__ ull fma2(ull a, ull b, ull c) {
    ull d;
    asm("fma.rn.f32x2 %0, %1, %2, %3;" : "=l"(d) : "l"(a), "l"(b), "l"(c));
    return d;
}
__device__ __forceinline__ ull pack2(float lo, float hi) {
    ull d;
    asm("mov.b64 %0, {%1, %2};" : "=l"(d) : "f"(lo), "f"(hi));
    return d;
}
__device__ __forceinline__ void unpack2(ull v, float& lo, float& hi) {
    asm("mov.b64 {%0, %1}, %2;" : "=f"(lo), "=f"(hi) : "l"(v));
}
__device__ __forceinline__ uint32_t cvt_tf32(float f) {
    uint32_t r;
    asm("cvt.rna.tf32.f32 %0, %1;" : "=r"(r) : "f"(f));
    return r;
}
__device__ __forceinline__ float ex2f(float x) {
    float r;
    asm("ex2.approx.f32 %0, %1;" : "=f"(r) : "f"(x));
    return r;
}
// returns {lo, hi} packed bf16x2 (PTX: first operand -> high half)
__device__ __forceinline__ uint32_t bf16pk(float hi, float lo) {
    uint32_t r;
    asm("cvt.rn.bf16x2.f32 %0, %1, %2;" : "=r"(r) : "f"(hi), "f"(lo));
    return r;
}
__device__ __forceinline__ void mma_tf32(float& d0, float& d1, float& d2, float& d3,
        uint32_t a0, uint32_t a1, uint32_t a2, uint32_t a3,
        uint32_t b0, uint32_t b1) {
    asm("mma.sync.aligned.m16n8k8.row.col.f32.tf32.tf32.f32 "
        "{%0,%1,%2,%3}, {%4,%5,%6,%7}, {%8,%9}, {%10,%11,%12,%13};"
        : "=f"(d0), "=f"(d1), "=f"(d2), "=f"(d3)
        : "r"(a0), "r"(a1), "r"(a2), "r"(a3), "r"(b0), "r"(b1),
          "f"(0.0f), "f"(0.0f), "f"(0.0f), "f"(0.0f));
}
__device__ __forceinline__ void mma_bf16(float* d,
        uint32_t a0, uint32_t a1, uint32_t a2, uint32_t a3,
        uint32_t b0, uint32_t b1) {
    asm("mma.sync.aligned.m16n8k16.row.col.f32.bf16.bf16.f32 "
        "{%0,%1,%2,%3}, {%4,%5,%6,%7}, {%8,%9}, {%0,%1,%2,%3};"
        : "+f"(d[0]), "+f"(d[1]), "+f"(d[2]), "+f"(d[3])
        : "r"(a0), "r"(a1), "r"(a2), "r"(a3), "r"(b0), "r"(b1));
}

#define PHI_PITCH 10                    // floats per phi row (pad kills conflicts)
#define G_PITCH_B 2064                  // bytes per g row (1032 bf16): banks 4a+b
#define SM_PHI_B  (MM * PHI_PITCH * 4)  // 40960
#define SM_ATTN   (SM_PHI_B + 32 * G_PITCH_B)   // 40960 + 66048 = 107008

// ---------------------------------------------------------------------------
// Kernel A: theta = (W_theta @ x + b_theta), stored [b][q][8]
// ---------------------------------------------------------------------------
__global__ void __launch_bounds__(256) theta_kernel(
        const float* __restrict__ x,
        const float* __restrict__ Wt,
        const float* __restrict__ bt) {
    __shared__ __align__(16) float WT[64 * 8];
    __shared__ float b_s[8];
    int tid = threadIdx.x;
    for (int i = tid; i < 512; i += 256) {
        int k = i & 7, c = i >> 3;
        WT[i] = Wt[k * 64 + c];
    }
    if (tid < 8) b_s[tid] = bt[tid];
    __syncthreads();

    int p = blockIdx.x * 256 + tid;
    int b = p >> 12;
    int q = p & 4095;
    const float* xp = x + (size_t)b * CC * NN + q;

    ull acc[4] = {0ull, 0ull, 0ull, 0ull};
    #pragma unroll 8
    for (int c = 0; c < 64; c++) {
        float xv = xp[(size_t)c * NN];
        ull v2 = pack2(xv, xv);
        const ulonglong2* wr = (const ulonglong2*)(WT + c * 8);
        ulonglong2 w0 = wr[0];
        ulonglong2 w1 = wr[1];
        acc[0] = fma2(v2, w0.x, acc[0]);
        acc[1] = fma2(v2, w0.y, acc[1]);
        acc[2] = fma2(v2, w1.x, acc[2]);
        acc[3] = fma2(v2, w1.y, acc[3]);
    }
    float o0, o1, o2, o3, o4, o5, o6, o7;
    unpack2(acc[0], o0, o1);
    unpack2(acc[1], o2, o3);
    unpack2(acc[2], o4, o5);
    unpack2(acc[3], o6, o7);
    float4* op = (float4*)(g_theta + (size_t)p * 8);
    op[0] = make_float4(o0 + b_s[0], o1 + b_s[1], o2 + b_s[2], o3 + b_s[3]);
    op[1] = make_float4(o4 + b_s[4], o5 + b_s[5], o6 + b_s[6], o7 + b_s[7]);
}

// ---------------------------------------------------------------------------
// Kernel B: phi = maxpool2(conv)+b -> [b][m][8] f32
//           g   = maxpool2(conv)+b -> [b][c'][m] bf16
// 4 lanes per pooled pixel (one per window position), shfl-max reduce.
// ---------------------------------------------------------------------------
__global__ void __launch_bounds__(256) pool_kernel(
        const float* __restrict__ x,
        const float* __restrict__ Wp, const float* __restrict__ bp,
        const float* __restrict__ Wg, const float* __restrict__ bg) {
    __shared__ __align__(16) float WT[64 * 40];
    __shared__ float bias_s[40];
    int tid = threadIdx.x;
    for (int i = tid; i < 2560; i += 256) {
        int o = i % 40, c = i / 40;
        WT[i] = (o < 8) ? Wp[o * 64 + c] : Wg[(o - 8) * 64 + c];
    }
    if (tid < 40) bias_s[tid] = (tid < 8) ? bp[tid] : bg[tid - 8];
    __syncthreads();

    int idx = blockIdx.x * 256 + tid;
    int pm = idx >> 2;          // pooled pixel
    int pos = idx & 3;          // window position
    int b = pm >> 10;
    int m = pm & 1023;
    int hp = m >> 5, wp = m & 31;
    int q = (2 * hp + (pos >> 1)) * 64 + 2 * wp + (pos & 1);
    const float* xb = x + (size_t)b * CC * NN + q;

    ull y[20];
    #pragma unroll
    for (int j = 0; j < 20; j++) y[j] = 0ull;
    for (int c = 0; c < 64; c++) {
        float xv = xb[(size_t)c * NN];
        ull v2 = pack2(xv, xv);
        const ulonglong2* wr = (const ulonglong2*)(WT + c * 40);
        #pragma unroll
        for (int j = 0; j < 10; j++) {
            ulonglong2 wv = wr[j];
            y[2 * j]     = fma2(v2, wv.x, y[2 * j]);
            y[2 * j + 1] = fma2(v2, wv.y, y[2 * j + 1]);
        }
    }
    float v[40];
    #pragma unroll
    for (int j = 0; j < 20; j++) unpack2(y[j], v[2 * j], v[2 * j + 1]);
    #pragma unroll
    for (int j = 0; j < 40; j++) {
        v[j] = fmaxf(v[j], __shfl_xor_sync(0xffffffffu, v[j], 1));
        v[j] = fmaxf(v[j], __shfl_xor_sync(0xffffffffu, v[j], 2));
    }
    if (pos == 0) {
        float* php = g_phi + (size_t)pm * 8;
        #pragma unroll
        for (int k = 0; k < 8; k++) php[k] = v[k] + bias_s[k];
        __nv_bfloat16* gp = g_gbf + (size_t)b * 32 * MM + m;
        #pragma unroll
        for (int j = 0; j < 32; j++)
            gp[(size_t)j * MM] = __float2bfloat16(v[8 + j] + bias_s[8 + j]);
    }
}

// ---------------------------------------------------------------------------
// Kernel C: fused flash attention on mma.sync tensor cores.
//   CTA = (batch, 128-query tile); 8 warps x 16 queries; loop 64 chunks of
//   16 keys. Per chunk: S = theta @ phi^T via 2x mma.tf32 (theta pre-scaled
//   by log2e), P = ex2(S) -> bf16 in regs (S accum frag == bf16 A frag),
//   O += P @ g^T via 4x mma.bf16. Denominator via quad shuffles.
// ---------------------------------------------------------------------------
__global__ void __launch_bounds__(256, 2) attn_kernel() {
    extern __shared__ __align__(16) char sm[];
    float* phi_s = (float*)sm;                 // [1024][PHI_PITCH] tf32 bits
    char* g_s = sm + SM_PHI_B;                 // 32 rows x G_PITCH_B

    int tid = threadIdx.x;
    int b = blockIdx.x >> 5;
    int qt = blockIdx.x & 31;

    // Load phi (cvt to tf32) and g (bf16) for this batch
    {
        const float4* ps = (const float4*)(g_phi + (size_t)b * MM * 8);
        for (int i = tid; i < 2048; i += 256) {
            float4 t = ps[i];
            int m = i >> 1, h = (i & 1) * 4;
            uint32_t* dst = (uint32_t*)(phi_s + m * PHI_PITCH + h);
            dst[0] = cvt_tf32(t.x);
            dst[1] = cvt_tf32(t.y);
            dst[2] = cvt_tf32(t.z);
            dst[3] = cvt_tf32(t.w);
        }
        const uint4* gs = (const uint4*)(g_gbf + (size_t)b * 32 * MM);
        for (int i = tid; i < 4096; i += 256) {
            int row = i >> 7, col = i & 127;
            *(uint4*)(g_s + row * G_PITCH_B + col * 16) = gs[i];
        }
    }
    __syncthreads();

    int w = tid >> 5, lane = tid & 31;
    int t4 = lane >> 2, tm4 = lane & 3;
    int q0 = qt * 128 + w * 16;

    // theta A-fragment (tf32), pre-scaled by log2(e)
    const float L2E = 1.4426950408889634f;
    const float* tp = g_theta + ((size_t)b * NN + q0) * 8;
    uint32_t ta0 = cvt_tf32(tp[t4 * 8 + tm4] * L2E);
    uint32_t ta1 = cvt_tf32(tp[(t4 + 8) * 8 + tm4] * L2E);
    uint32_t ta2 = cvt_tf32(tp[t4 * 8 + tm4 + 4] * L2E);
    uint32_t ta3 = cvt_tf32(tp[(t4 + 8) * 8 + tm4 + 4] * L2E);

    float o[16];
    #pragma unroll
    for (int j = 0; j < 16; j++) o[j] = 0.0f;
    float den_lo = 0.0f, den_hi = 0.0f;

    #pragma unroll 2
    for (int ch = 0; ch < 64; ch++) {
        int m0 = ch * 16;
        // phi B-fragments (two n8 tiles of keys)
        const uint32_t* pb = (const uint32_t*)(phi_s + (m0 + t4) * PHI_PITCH + tm4);
        uint32_t pb0 = pb[0], pb1 = pb[4];
        const uint32_t* pc = pb + 8 * PHI_PITCH;
        uint32_t pc0 = pc[0], pc1 = pc[4];

        float s0, s1, s2, s3, s4, s5, s6, s7;
        mma_tf32(s0, s1, s2, s3, ta0, ta1, ta2, ta3, pb0, pb1);
        mma_tf32(s4, s5, s6, s7, ta0, ta1, ta2, ta3, pc0, pc1);

        float e0 = ex2f(s0), e1 = ex2f(s1), e2 = ex2f(s2), e3 = ex2f(s3);
        float e4 = ex2f(s4), e5 = ex2f(s5), e6 = ex2f(s6), e7 = ex2f(s7);
        den_lo += (e0 + e1) + (e4 + e5);
        den_hi += (e2 + e3) + (e6 + e7);

        // P A-fragment (bf16x2): S accum layout == bf16 A layout
        uint32_t pa0 = bf16pk(e1, e0);
        uint32_t pa1 = bf16pk(e3, e2);
        uint32_t pa2 = bf16pk(e5, e4);
        uint32_t pa3 = bf16pk(e7, e6);

        // O += P @ g^T over 4 channel tiles
        #pragma unroll
        for (int nt = 0; nt < 4; nt++) {
            const char* gb = g_s + (nt * 8 + t4) * G_PITCH_B + (m0 + 2 * tm4) * 2;
            uint32_t gb0 = *(const uint32_t*)gb;
            uint32_t gb1 = *(const uint32_t*)(gb + 16);
            mma_bf16(o + nt * 4, pa0, pa1, pa2, pa3, gb0, gb1);
        }
    }

    den_lo += __shfl_xor_sync(0xffffffffu, den_lo, 1);
    den_lo += __shfl_xor_sync(0xffffffffu, den_lo, 2);
    den_hi += __shfl_xor_sync(0xffffffffu, den_hi, 1);
    den_hi += __shfl_xor_sync(0xffffffffu, den_hi, 2);
    float il = 1.0f / den_lo;
    float ih = 1.0f / den_hi;

    float* ob = g_oT + ((size_t)b * NN + q0) * 32;
    #pragma unroll
    for (int nt = 0; nt < 4; nt++) {
        int c0 = nt * 8 + 2 * tm4;
        *(float2*)(ob + t4 * 32 + c0)       = make_float2(o[nt * 4] * il,
                                                          o[nt * 4 + 1] * il);
        *(float2*)(ob + (t4 + 8) * 32 + c0) = make_float2(o[nt * 4 + 2] * ih,
                                                          o[nt * 4 + 3] * ih);
    }
}

// ---------------------------------------------------------------------------
// Kernel D: out = gamma * (W_o @ o + b_o) + inputs  (4 threads/pixel, 16 co ea)
// ---------------------------------------------------------------------------
__global__ void __launch_bounds__(512) out_kernel(
        const float* __restrict__ x,
        const float* __restrict__ Wo, const float* __restrict__ bo,
        const float* __restrict__ gam,
        float* __restrict__ out) {
    __shared__ __align__(16) float WT[32 * 64];   // [ci][co]
    __shared__ float b_s[64];
    int tid = threadIdx.x;
    for (int i = tid; i < 2048; i += 512) {
        int co = i >> 5, ci = i & 31;
        WT[ci * 64 + co] = Wo[i];
    }
    if (tid < 64) b_s[tid] = bo[tid];
    __syncthreads();

    int idx = blockIdx.x * 512 + tid;
    int gp = idx >> 2;          // pixel
    int qu = idx & 3;           // channel quarter
    int b = gp >> 12;
    int q = gp & 4095;

    float ov[32];
    {
        const float4* ov4 = (const float4*)(g_oT + (size_t)gp * 32);
        #pragma unroll
        for (int j = 0; j < 8; j++) {
            float4 t = ov4[j];
            ov[4 * j]     = t.x;
            ov[4 * j + 1] = t.y;
            ov[4 * j + 2] = t.z;
            ov[4 * j + 3] = t.w;
        }
    }

    ull acc[8];
    #pragma unroll
    for (int j = 0; j < 8; j++) acc[j] = 0ull;

    #pragma unroll 4
    for (int ci = 0; ci < 32; ci++) {
        ull v2 = pack2(ov[ci], ov[ci]);
        const ulonglong2* wr = (const ulonglong2*)(WT + ci * 64 + qu * 16);
        #pragma unroll
        for (int j = 0; j < 4; j++) {
            ulonglong2 wv = wr[j];
            acc[2 * j]     = fma2(v2, wv.x, acc[2 * j]);
            acc[2 * j + 1] = fma2(v2, wv.y, acc[2 * j + 1]);
        }
    }

    float gma = gam[0];
    int co0 = qu * 16;
    const float* xp = x + (size_t)b * CC * NN + q;
    float* outp = out + (size_t)b * CC * NN + q;
    #pragma unroll
    for (int j = 0; j < 8; j++) {
        float lo, hi;
        unpack2(acc[j], lo, hi);
        int co = co0 + 2 * j;
        outp[(size_t)co * NN]       = gma * (lo + b_s[co])     + xp[(size_t)co * NN];
        outp[(size_t)(co + 1) * NN] = gma * (hi + b_s[co + 1]) + xp[(size_t)(co + 1) * NN];
    }
}

// ---------------------------------------------------------------------------
extern "C" void kernel_launch(void* const* d_in, const int* in_sizes, int n_in,
                              void* d_out, int out_size) {
    const float* x   = (const float*)d_in[0];
    const float* Wt  = (const float*)d_in[1];
    const float* bt  = (const float*)d_in[2];
    const float* Wp  = (const float*)d_in[3];
    const float* bp  = (const float*)d_in[4];
    const float* Wg  = (const float*)d_in[5];
    const float* bg  = (const float*)d_in[6];
    const float* Wo  = (const float*)d_in[7];
    const float* bo  = (const float*)d_in[8];
    const float* gam = (const float*)d_in[9];
    float* out = (float*)d_out;

    theta_kernel<<<BB * NN / 256, 256>>>(x, Wt, bt);
    pool_kernel<<<BB * MM * 4 / 256, 256>>>(x, Wp, bp, Wg, bg);

    cudaFuncSetAttribute(attn_kernel,
                         cudaFuncAttributeMaxDynamicSharedMemorySize, SM_ATTN);
    attn_kernel<<<BB * 32, 256, SM_ATTN>>>();

    out_kernel<<<BB * NN * 4 / 512, 512>>>(x, Wo, bo, gam, out);
}

// round 10
// speedup vs baseline: 2.7290x; 1.4012x over previous
#include <cuda_runtime.h>
#include <cuda_bf16.h>
#include <cstdint>

#define BB 16
#define CC 64
#define NN 4096   // H*W
#define MM 1024   // N/4

// Scratch (allocation-free: __device__ globals)
__device__ __align__(16) float g_theta[BB * NN * 8];              // [b][q][8]
__device__ __align__(16) float g_phi[BB * MM * 8];                // [b][m][8]
__device__ __align__(16) __nv_bfloat16 g_gbf[BB * 32 * MM];       // [b][c'][m] bf16
__device__ __align__(16) float g_oT[(size_t)BB * 32 * NN];        // [b][ci][q]  (channel-major)

typedef unsigned long long ull;

__device__ __forceinline__ ull fma2(ull a, ull b, ull c) {
    ull d;
    asm("fma.rn.f32x2 %0, %1, %2, %3;" : "=l"(d) : "l"(a), "l"(b), "l"(c));
    return d;
}
__device__ __forceinline__ ull pack2(float lo, float hi) {
    ull d;
    asm("mov.b64 %0, {%1, %2};" : "=l"(d) : "f"(lo), "f"(hi));
    return d;
}
__device__ __forceinline__ void unpack2(ull v, float& lo, float& hi) {
    asm("mov.b64 {%0, %1}, %2;" : "=f"(lo), "=f"(hi) : "l"(v));
}
__device__ __forceinline__ uint32_t cvt_tf32(float f) {
    uint32_t r;
    asm("cvt.rna.tf32.f32 %0, %1;" : "=r"(r) : "f"(f));
    return r;
}
__device__ __forceinline__ float ex2f(float x) {
    float r;
    asm("ex2.approx.f32 %0, %1;" : "=f"(r) : "f"(x));
    return r;
}
// returns {lo, hi} packed bf16x2 (PTX: first operand -> high half)
__device__ __forceinline__ uint32_t bf16pk(float hi, float lo) {
    uint32_t r;
    asm("cvt.rn.bf16x2.f32 %0, %1, %2;" : "=r"(r) : "f"(hi), "f"(lo));
    return r;
}
__device__ __forceinline__ void mma_tf32(float& d0, float& d1, float& d2, float& d3,
        uint32_t a0, uint32_t a1, uint32_t a2, uint32_t a3,
        uint32_t b0, uint32_t b1) {
    asm("mma.sync.aligned.m16n8k8.row.col.f32.tf32.tf32.f32 "
        "{%0,%1,%2,%3}, {%4,%5,%6,%7}, {%8,%9}, {%10,%11,%12,%13};"
        : "=f"(d0), "=f"(d1), "=f"(d2), "=f"(d3)
        : "r"(a0), "r"(a1), "r"(a2), "r"(a3), "r"(b0), "r"(b1),
          "f"(0.0f), "f"(0.0f), "f"(0.0f), "f"(0.0f));
}
__device__ __forceinline__ void mma_bf16(float* d,
        uint32_t a0, uint32_t a1, uint32_t a2, uint32_t a3,
        uint32_t b0, uint32_t b1) {
    asm("mma.sync.aligned.m16n8k16.row.col.f32.bf16.bf16.f32 "
        "{%0,%1,%2,%3}, {%4,%5,%6,%7}, {%8,%9}, {%0,%1,%2,%3};"
        : "+f"(d[0]), "+f"(d[1]), "+f"(d[2]), "+f"(d[3])
        : "r"(a0), "r"(a1), "r"(a2), "r"(a3), "r"(b0), "r"(b1));
}

#define PHI_PITCH 10                    // floats per phi row (pad kills conflicts)
#define G_PITCH_B 2064                  // bytes per g row (1032 bf16): banks 4a+b
#define SM_PHI_B  (MM * PHI_PITCH * 4)  // 40960
#define SM_ATTN   (SM_PHI_B + 32 * G_PITCH_B)   // 40960 + 66048 = 107008

// ---------------------------------------------------------------------------
// Kernel A: theta = (W_theta @ x + b_theta), stored [b][q][8]
// ---------------------------------------------------------------------------
__global__ void __launch_bounds__(256) theta_kernel(
        const float* __restrict__ x,
        const float* __restrict__ Wt,
        const float* __restrict__ bt) {
    __shared__ __align__(16) float WT[64 * 8];
    __shared__ float b_s[8];
    int tid = threadIdx.x;
    for (int i = tid; i < 512; i += 256) {
        int k = i & 7, c = i >> 3;
        WT[i] = Wt[k * 64 + c];
    }
    if (tid < 8) b_s[tid] = bt[tid];
    __syncthreads();

    int p = blockIdx.x * 256 + tid;
    int b = p >> 12;
    int q = p & 4095;
    const float* xp = x + (size_t)b * CC * NN + q;

    ull acc[4] = {0ull, 0ull, 0ull, 0ull};
    #pragma unroll 8
    for (int c = 0; c < 64; c++) {
        float xv = xp[(size_t)c * NN];
        ull v2 = pack2(xv, xv);
        const ulonglong2* wr = (const ulonglong2*)(WT + c * 8);
        ulonglong2 w0 = wr[0];
        ulonglong2 w1 = wr[1];
        acc[0] = fma2(v2, w0.x, acc[0]);
        acc[1] = fma2(v2, w0.y, acc[1]);
        acc[2] = fma2(v2, w1.x, acc[2]);
        acc[3] = fma2(v2, w1.y, acc[3]);
    }
    float o0, o1, o2, o3, o4, o5, o6, o7;
    unpack2(acc[0], o0, o1);
    unpack2(acc[1], o2, o3);
    unpack2(acc[2], o4, o5);
    unpack2(acc[3], o6, o7);
    float4* op = (float4*)(g_theta + (size_t)p * 8);
    op[0] = make_float4(o0 + b_s[0], o1 + b_s[1], o2 + b_s[2], o3 + b_s[3]);
    op[1] = make_float4(o4 + b_s[4], o5 + b_s[5], o6 + b_s[6], o7 + b_s[7]);
}

// ---------------------------------------------------------------------------
// Kernel B: phi = maxpool2(conv)+b -> [b][m][8] f32
//           g   = maxpool2(conv)+b -> [b][c'][m] bf16
// 4 lanes per pooled pixel (one per window position), shfl-max reduce.
// ---------------------------------------------------------------------------
__global__ void __launch_bounds__(256) pool_kernel(
        const float* __restrict__ x,
        const float* __restrict__ Wp, const float* __restrict__ bp,
        const float* __restrict__ Wg, const float* __restrict__ bg) {
    __shared__ __align__(16) float WT[64 * 40];
    __shared__ float bias_s[40];
    int tid = threadIdx.x;
    for (int i = tid; i < 2560; i += 256) {
        int o = i % 40, c = i / 40;
        WT[i] = (o < 8) ? Wp[o * 64 + c] : Wg[(o - 8) * 64 + c];
    }
    if (tid < 40) bias_s[tid] = (tid < 8) ? bp[tid] : bg[tid - 8];
    __syncthreads();

    int idx = blockIdx.x * 256 + tid;
    int pm = idx >> 2;          // pooled pixel
    int pos = idx & 3;          // window position
    int b = pm >> 10;
    int m = pm & 1023;
    int hp = m >> 5, wp = m & 31;
    int q = (2 * hp + (pos >> 1)) * 64 + 2 * wp + (pos & 1);
    const float* xb = x + (size_t)b * CC * NN + q;

    ull y[20];
    #pragma unroll
    for (int j = 0; j < 20; j++) y[j] = 0ull;
    for (int c = 0; c < 64; c++) {
        float xv = xb[(size_t)c * NN];
        ull v2 = pack2(xv, xv);
        const ulonglong2* wr = (const ulonglong2*)(WT + c * 40);
        #pragma unroll
        for (int j = 0; j < 10; j++) {
            ulonglong2 wv = wr[j];
            y[2 * j]     = fma2(v2, wv.x, y[2 * j]);
            y[2 * j + 1] = fma2(v2, wv.y, y[2 * j + 1]);
        }
    }
    float v[40];
    #pragma unroll
    for (int j = 0; j < 20; j++) unpack2(y[j], v[2 * j], v[2 * j + 1]);
    #pragma unroll
    for (int j = 0; j < 40; j++) {
        v[j] = fmaxf(v[j], __shfl_xor_sync(0xffffffffu, v[j], 1));
        v[j] = fmaxf(v[j], __shfl_xor_sync(0xffffffffu, v[j], 2));
    }
    if (pos == 0) {
        float* php = g_phi + (size_t)pm * 8;
        #pragma unroll
        for (int k = 0; k < 8; k++) php[k] = v[k] + bias_s[k];
        __nv_bfloat16* gp = g_gbf + (size_t)b * 32 * MM + m;
        #pragma unroll
        for (int j = 0; j < 32; j++)
            gp[(size_t)j * MM] = __float2bfloat16(v[8 + j] + bias_s[8 + j]);
    }
}

// ---------------------------------------------------------------------------
// Kernel C: fused flash attention on mma.sync tensor cores.
//   CTA = (batch, 128-query tile); 8 warps x 16 queries; loop 64 chunks of
//   16 keys. Per chunk: S = theta @ phi^T via 2x mma.tf32 (theta pre-scaled
//   by log2e), P = ex2(S) -> bf16 in regs (S accum frag == bf16 A frag),
//   O += P @ g^T via 4x mma.bf16. Denominator via quad shuffles.
//   Epilogue writes o to channel-major g_oT [b][ci][q].
// ---------------------------------------------------------------------------
__global__ void __launch_bounds__(256, 2) attn_kernel() {
    extern __shared__ __align__(16) char sm[];
    float* phi_s = (float*)sm;                 // [1024][PHI_PITCH] tf32 bits
    char* g_s = sm + SM_PHI_B;                 // 32 rows x G_PITCH_B

    int tid = threadIdx.x;
    int b = blockIdx.x >> 5;
    int qt = blockIdx.x & 31;

    // Load phi (cvt to tf32) and g (bf16) for this batch
    {
        const float4* ps = (const float4*)(g_phi + (size_t)b * MM * 8);
        for (int i = tid; i < 2048; i += 256) {
            float4 t = ps[i];
            int m = i >> 1, h = (i & 1) * 4;
            uint32_t* dst = (uint32_t*)(phi_s + m * PHI_PITCH + h);
            dst[0] = cvt_tf32(t.x);
            dst[1] = cvt_tf32(t.y);
            dst[2] = cvt_tf32(t.z);
            dst[3] = cvt_tf32(t.w);
        }
        const uint4* gs = (const uint4*)(g_gbf + (size_t)b * 32 * MM);
        for (int i = tid; i < 4096; i += 256) {
            int row = i >> 7, col = i & 127;
            *(uint4*)(g_s + row * G_PITCH_B + col * 16) = gs[i];
        }
    }
    __syncthreads();

    int w = tid >> 5, lane = tid & 31;
    int t4 = lane >> 2, tm4 = lane & 3;
    int q0 = qt * 128 + w * 16;

    // theta A-fragment (tf32), pre-scaled by log2(e)
    const float L2E = 1.4426950408889634f;
    const float* tp = g_theta + ((size_t)b * NN + q0) * 8;
    uint32_t ta0 = cvt_tf32(tp[t4 * 8 + tm4] * L2E);
    uint32_t ta1 = cvt_tf32(tp[(t4 + 8) * 8 + tm4] * L2E);
    uint32_t ta2 = cvt_tf32(tp[t4 * 8 + tm4 + 4] * L2E);
    uint32_t ta3 = cvt_tf32(tp[(t4 + 8) * 8 + tm4 + 4] * L2E);

    float o[16];
    #pragma unroll
    for (int j = 0; j < 16; j++) o[j] = 0.0f;
    float den_lo = 0.0f, den_hi = 0.0f;

    #pragma unroll 2
    for (int ch = 0; ch < 64; ch++) {
        int m0 = ch * 16;
        // phi B-fragments (two n8 tiles of keys)
        const uint32_t* pb = (const uint32_t*)(phi_s + (m0 + t4) * PHI_PITCH + tm4);
        uint32_t pb0 = pb[0], pb1 = pb[4];
        const uint32_t* pc = pb + 8 * PHI_PITCH;
        uint32_t pc0 = pc[0], pc1 = pc[4];

        float s0, s1, s2, s3, s4, s5, s6, s7;
        mma_tf32(s0, s1, s2, s3, ta0, ta1, ta2, ta3, pb0, pb1);
        mma_tf32(s4, s5, s6, s7, ta0, ta1, ta2, ta3, pc0, pc1);

        float e0 = ex2f(s0), e1 = ex2f(s1), e2 = ex2f(s2), e3 = ex2f(s3);
        float e4 = ex2f(s4), e5 = ex2f(s5), e6 = ex2f(s6), e7 = ex2f(s7);
        den_lo += (e0 + e1) + (e4 + e5);
        den_hi += (e2 + e3) + (e6 + e7);

        // P A-fragment (bf16x2): S accum layout == bf16 A layout
        uint32_t pa0 = bf16pk(e1, e0);
        uint32_t pa1 = bf16pk(e3, e2);
        uint32_t pa2 = bf16pk(e5, e4);
        uint32_t pa3 = bf16pk(e7, e6);

        // O += P @ g^T over 4 channel tiles
        #pragma unroll
        for (int nt = 0; nt < 4; nt++) {
            const char* gb = g_s + (nt * 8 + t4) * G_PITCH_B + (m0 + 2 * tm4) * 2;
            uint32_t gb0 = *(const uint32_t*)gb;
            uint32_t gb1 = *(const uint32_t*)(gb + 16);
            mma_bf16(o + nt * 4, pa0, pa1, pa2, pa3, gb0, gb1);
        }
    }

    den_lo += __shfl_xor_sync(0xffffffffu, den_lo, 1);
    den_lo += __shfl_xor_sync(0xffffffffu, den_lo, 2);
    den_hi += __shfl_xor_sync(0xffffffffu, den_hi, 1);
    den_hi += __shfl_xor_sync(0xffffffffu, den_hi, 2);
    float il = 1.0f / den_lo;
    float ih = 1.0f / den_hi;

    // Write channel-major: g_oT[b][c][q]
    int qglob = q0 + t4;
    float* ob = g_oT + (size_t)b * 32 * NN;
    #pragma unroll
    for (int nt = 0; nt < 4; nt++) {
        int c0 = nt * 8 + 2 * tm4;
        ob[(size_t)c0 * NN + qglob]           = o[nt * 4]     * il;
        ob[(size_t)(c0 + 1) * NN + qglob]     = o[nt * 4 + 1] * il;
        ob[(size_t)c0 * NN + qglob + 8]       = o[nt * 4 + 2] * ih;
        ob[(size_t)(c0 + 1) * NN + qglob + 8] = o[nt * 4 + 3] * ih;
    }
}

// ---------------------------------------------------------------------------
// Kernel D: out = gamma * (W_o @ o + b_o) + inputs
//   1 thread/pixel, 256 pixels/block. o-tile staged in smem (coalesced f4
//   loads from channel-major g_oT); all x loads and out stores are
//   warp-coalesced (lanes = consecutive q, fixed channel).
// ---------------------------------------------------------------------------
__global__ void __launch_bounds__(256) out_kernel(
        const float* __restrict__ x,
        const float* __restrict__ Wo, const float* __restrict__ bo,
        const float* __restrict__ gam,
        float* __restrict__ out) {
    __shared__ __align__(16) float WT[32 * 64];   // [ci][co]
    __shared__ float b_s[64];
    __shared__ __align__(16) float o_s[32 * 256]; // [ci][ql]
    int tid = threadIdx.x;
    for (int i = tid; i < 2048; i += 256) {
        int co = i >> 5, ci = i & 31;
        WT[ci * 64 + co] = Wo[i];
    }
    if (tid < 64) b_s[tid] = bo[tid];

    int p0 = blockIdx.x * 256;          // first global pixel of tile
    int b = p0 >> 12;
    int lq0 = p0 & 4095;
    {
        const float* ob = g_oT + (size_t)b * 32 * NN + lq0;
        for (int i = tid; i < 2048; i += 256) {
            int ci = i >> 6, grp = i & 63;
            float4 v = *(const float4*)(ob + (size_t)ci * NN + grp * 4);
            *(float4*)(o_s + ci * 256 + grp * 4) = v;
        }
    }
    __syncthreads();

    int q = lq0 + tid;

    ull acc[32];
    #pragma unroll
    for (int j = 0; j < 32; j++) acc[j] = 0ull;

    #pragma unroll 2
    for (int ci = 0; ci < 32; ci++) {
        float ov = o_s[ci * 256 + tid];
        ull v2 = pack2(ov, ov);
        const ulonglong2* wr = (const ulonglong2*)(WT + ci * 64);
        #pragma unroll
        for (int j = 0; j < 16; j++) {
            ulonglong2 wv = wr[j];
            acc[2 * j]     = fma2(v2, wv.x, acc[2 * j]);
            acc[2 * j + 1] = fma2(v2, wv.y, acc[2 * j + 1]);
        }
    }

    float gma = gam[0];
    const float* xp = x + (size_t)b * CC * NN + q;
    float* outp = out + (size_t)b * CC * NN + q;
    #pragma unroll
    for (int j = 0; j < 32; j++) {
        float lo, hi;
        unpack2(acc[j], lo, hi);
        int co = 2 * j;
        outp[(size_t)co * NN]       = gma * (lo + b_s[co])     + xp[(size_t)co * NN];
        outp[(size_t)(co + 1) * NN] = gma * (hi + b_s[co + 1]) + xp[(size_t)(co + 1) * NN];
    }
}

// ---------------------------------------------------------------------------
extern "C" void kernel_launch(void* const* d_in, const int* in_sizes, int n_in,
                              void* d_out, int out_size) {
    const float* x   = (const float*)d_in[0];
    const float* Wt  = (const float*)d_in[1];
    const float* bt  = (const float*)d_in[2];
    const float* Wp  = (const float*)d_in[3];
    const float* bp  = (const float*)d_in[4];
    const float* Wg  = (const float*)d_in[5];
    const float* bg  = (const float*)d_in[6];
    const float* Wo  = (const float*)d_in[7];
    const float* bo  = (const float*)d_in[8];
    const float* gam = (const float*)d_in[9];
    float* out = (float*)d_out;

    theta_kernel<<<BB * NN / 256, 256>>>(x, Wt, bt);
    pool_kernel<<<BB * MM * 4 / 256, 256>>>(x, Wp, bp, Wg, bg);

    cudaFuncSetAttribute(attn_kernel,
                         cudaFuncAttributeMaxDynamicSharedMemorySize, SM_ATTN);
    attn_kernel<<<BB * 32, 256, SM_ATTN>>>();

    out_kernel<<<BB * NN / 256, 256>>>(x, Wo, bo, gam, out);
}

// round 12
// speedup vs baseline: 3.2393x; 1.1870x over previous
#include <cuda_runtime.h>
#include <cuda_bf16.h>
#include <cstdint>

#define BB 16
#define CC 64
#define NN 4096   // H*W
#define MM 1024   // N/4

// Scratch (allocation-free: __device__ globals)
__device__ __align__(16) float g_theta[BB * NN * 8];              // [b][q][8]
__device__ __align__(16) float g_phi[BB * MM * 8];                // [b][m][8]
__device__ __align__(16) __nv_bfloat16 g_gbf[BB * 32 * MM];       // [b][c'][m] bf16

typedef unsigned long long ull;

__device__ __forceinline__ ull fma2(ull a, ull b, ull c) {
    ull d;
    asm("fma.rn.f32x2 %0, %1, %2, %3;" : "=l"(d) : "l"(a), "l"(b), "l"(c));
    return d;
}
__device__ __forceinline__ ull pack2(float lo, float hi) {
    ull d;
    asm("mov.b64 %0, {%1, %2};" : "=l"(d) : "f"(lo), "f"(hi));
    return d;
}
__device__ __forceinline__ void unpack2(ull v, float& lo, float& hi) {
    asm("mov.b64 {%0, %1}, %2;" : "=f"(lo), "=f"(hi) : "l"(v));
}
__device__ __forceinline__ uint32_t cvt_tf32(float f) {
    uint32_t r;
    asm("cvt.rna.tf32.f32 %0, %1;" : "=r"(r) : "f"(f));
    return r;
}
__device__ __forceinline__ float ex2f(float x) {
    float r;
    asm("ex2.approx.f32 %0, %1;" : "=f"(r) : "f"(x));
    return r;
}
// returns {lo, hi} packed bf16x2 (PTX: first operand -> high half)
__device__ __forceinline__ uint32_t bf16pk(float hi, float lo) {
    uint32_t r;
    asm("cvt.rn.bf16x2.f32 %0, %1, %2;" : "=r"(r) : "f"(hi), "f"(lo));
    return r;
}
__device__ __forceinline__ void mma_tf32(float& d0, float& d1, float& d2, float& d3,
        uint32_t a0, uint32_t a1, uint32_t a2, uint32_t a3,
        uint32_t b0, uint32_t b1) {
    asm("mma.sync.aligned.m16n8k8.row.col.f32.tf32.tf32.f32 "
        "{%0,%1,%2,%3}, {%4,%5,%6,%7}, {%8,%9}, {%10,%11,%12,%13};"
        : "=f"(d0), "=f"(d1), "=f"(d2), "=f"(d3)
        : "r"(a0), "r"(a1), "r"(a2), "r"(a3), "r"(b0), "r"(b1),
          "f"(0.0f), "f"(0.0f), "f"(0.0f), "f"(0.0f));
}
__device__ __forceinline__ void mma_bf16(float* d,
        uint32_t a0, uint32_t a1, uint32_t a2, uint32_t a3,
        uint32_t b0, uint32_t b1) {
    asm("mma.sync.aligned.m16n8k16.row.col.f32.bf16.bf16.f32 "
        "{%0,%1,%2,%3}, {%4,%5,%6,%7}, {%8,%9}, {%0,%1,%2,%3};"
        : "+f"(d[0]), "+f"(d[1]), "+f"(d[2]), "+f"(d[3])
        : "r"(a0), "r"(a1), "r"(a2), "r"(a3), "r"(b0), "r"(b1));
}

#define PHI_PITCH 10                    // floats per phi row (pad kills conflicts)
#define G_PITCH_B 2064                  // bytes per g row (1032 bf16): conflict-free
#define SM_PHI_B  (MM * PHI_PITCH * 4)  // 40960
#define SO_G      SM_PHI_B
#define SO_WO     (SO_G + 32 * G_PITCH_B)       // 107008; 64 rows x 72B
#define SO_BIAS   (SO_WO + 64 * 72)             // 111616; 64 floats
#define SM_ATTN   (SO_BIAS + 256)               // 111872

// ---------------------------------------------------------------------------
// Kernel 1: fused theta/phi/g. One thread per (pooled window, position).
//   Each thread convs its own pixel: theta[8] (stored for its q) and
//   phi/g[40] (maxpooled over the quad via shuffles, pos 0 stores).
// ---------------------------------------------------------------------------
__global__ void __launch_bounds__(256) pre_kernel(
        const float* __restrict__ x,
        const float* __restrict__ Wt, const float* __restrict__ bt,
        const float* __restrict__ Wp, const float* __restrict__ bp,
        const float* __restrict__ Wg, const float* __restrict__ bg) {
    __shared__ __align__(16) float WT[64 * 48];  // [c][o]: 0-7 th, 8-15 phi, 16-47 g
    __shared__ float b_s[48];
    int tid = threadIdx.x;
    for (int i = tid; i < 3072; i += 256) {
        int o = i % 48, c = i / 48;
        WT[i] = (o < 8) ? Wt[o * 64 + c]
              : (o < 16) ? Wp[(o - 8) * 64 + c]
                         : Wg[(o - 16) * 64 + c];
    }
    if (tid < 48) b_s[tid] = (tid < 8) ? bt[tid]
                           : (tid < 16) ? bp[tid - 8] : bg[tid - 16];
    __syncthreads();

    int idx = blockIdx.x * 256 + tid;
    int pm = idx >> 2;          // pooled pixel
    int pos = idx & 3;          // window position
    int b = pm >> 10;
    int m = pm & 1023;
    int hp = m >> 5, wp = m & 31;
    int q = (2 * hp + (pos >> 1)) * 64 + 2 * wp + (pos & 1);
    const float* xb = x + (size_t)b * CC * NN + q;

    ull y[24];
    #pragma unroll
    for (int j = 0; j < 24; j++) y[j] = 0ull;
    for (int c = 0; c < 64; c++) {
        float xv = xb[(size_t)c * NN];
        ull v2 = pack2(xv, xv);
        const ulonglong2* wr = (const ulonglong2*)(WT + c * 48);
        #pragma unroll
        for (int j = 0; j < 12; j++) {
            ulonglong2 wv = wr[j];
            y[2 * j]     = fma2(v2, wv.x, y[2 * j]);
            y[2 * j + 1] = fma2(v2, wv.y, y[2 * j + 1]);
        }
    }
    float v[48];
    #pragma unroll
    for (int j = 0; j < 24; j++) unpack2(y[j], v[2 * j], v[2 * j + 1]);

    // theta: every thread stores its own pixel
    {
        float4* op = (float4*)(g_theta + ((size_t)b * NN + q) * 8);
        op[0] = make_float4(v[0] + b_s[0], v[1] + b_s[1],
                            v[2] + b_s[2], v[3] + b_s[3]);
        op[1] = make_float4(v[4] + b_s[4], v[5] + b_s[5],
                            v[6] + b_s[6], v[7] + b_s[7]);
    }
    // phi/g: maxpool across the quad
    #pragma unroll
    for (int j = 8; j < 48; j++) {
        v[j] = fmaxf(v[j], __shfl_xor_sync(0xffffffffu, v[j], 1));
        v[j] = fmaxf(v[j], __shfl_xor_sync(0xffffffffu, v[j], 2));
    }
    if (pos == 0) {
        float* php = g_phi + (size_t)pm * 8;
        #pragma unroll
        for (int k = 0; k < 8; k++) php[k] = v[8 + k] + b_s[8 + k];
        __nv_bfloat16* gp = g_gbf + (size_t)b * 32 * MM + m;
        #pragma unroll
        for (int j = 0; j < 32; j++)
            gp[(size_t)j * MM] = __float2bfloat16(v[16 + j] + b_s[16 + j]);
    }
}

// ---------------------------------------------------------------------------
// Kernel 2: fused flash attention + output projection + residual.
//   Mainloop (per 16-key chunk): S = theta@phi^T (2x mma.tf32, theta
//   pre-scaled by log2e), P = ex2(S) -> bf16 A-frags in regs,
//   O += P@g^T (4x mma.bf16). Epilogue: O frags * 1/denom -> bf16 A-frags,
//   out_tile = O @ W_o^T (2x mma.bf16 per 8-co tile),
//   out = gamma*(out_tile + b_o) + x written directly.
// ---------------------------------------------------------------------------
__global__ void __launch_bounds__(256, 2) attn_kernel(
        const float* __restrict__ x,
        const float* __restrict__ Wo, const float* __restrict__ bo,
        const float* __restrict__ gam,
        float* __restrict__ out) {
    extern __shared__ __align__(16) char sm[];
    float* phi_s = (float*)sm;                 // [1024][PHI_PITCH] tf32 bits
    char* g_s = sm + SO_G;                     // 32 rows x G_PITCH_B
    char* wo_s = sm + SO_WO;                   // 64 rows x 72B (bf16 pairs)
    float* b_s = (float*)(sm + SO_BIAS);       // 64 floats

    int tid = threadIdx.x;
    int b = blockIdx.x >> 5;
    int qt = blockIdx.x & 31;

    // Stage phi (tf32), g (bf16), W_o (bf16 pairs), bias
    {
        const float4* ps = (const float4*)(g_phi + (size_t)b * MM * 8);
        for (int i = tid; i < 2048; i += 256) {
            float4 t = ps[i];
            int m = i >> 1, h = (i & 1) * 4;
            uint32_t* dst = (uint32_t*)(phi_s + m * PHI_PITCH + h);
            dst[0] = cvt_tf32(t.x);
            dst[1] = cvt_tf32(t.y);
            dst[2] = cvt_tf32(t.z);
            dst[3] = cvt_tf32(t.w);
        }
        const uint4* gs = (const uint4*)(g_gbf + (size_t)b * 32 * MM);
        for (int i = tid; i < 4096; i += 256) {
            int row = i >> 7, col = i & 127;
            *(uint4*)(g_s + row * G_PITCH_B + col * 16) = gs[i];
        }
        for (int i = tid; i < 1024; i += 256) {        // W_o: [co][ci pair]
            int co = i >> 4, pr = i & 15;
            float lo = Wo[co * 32 + 2 * pr];
            float hi = Wo[co * 32 + 2 * pr + 1];
            *(uint32_t*)(wo_s + co * 72 + pr * 4) = bf16pk(hi, lo);
        }
        if (tid < 64) b_s[tid] = bo[tid];
    }
    __syncthreads();

    int w = tid >> 5, lane = tid & 31;
    int t4 = lane >> 2, tm4 = lane & 3;
    int q0 = qt * 128 + w * 16;

    // theta A-fragment (tf32), pre-scaled by log2(e)
    const float L2E = 1.4426950408889634f;
    const float* tp = g_theta + ((size_t)b * NN + q0) * 8;
    uint32_t ta0 = cvt_tf32(tp[t4 * 8 + tm4] * L2E);
    uint32_t ta1 = cvt_tf32(tp[(t4 + 8) * 8 + tm4] * L2E);
    uint32_t ta2 = cvt_tf32(tp[t4 * 8 + tm4 + 4] * L2E);
    uint32_t ta3 = cvt_tf32(tp[(t4 + 8) * 8 + tm4 + 4] * L2E);

    float o[16];
    #pragma unroll
    for (int j = 0; j < 16; j++) o[j] = 0.0f;
    float den_lo = 0.0f, den_hi = 0.0f;

    #pragma unroll 2
    for (int ch = 0; ch < 64; ch++) {
        int m0 = ch * 16;
        const uint32_t* pb = (const uint32_t*)(phi_s + (m0 + t4) * PHI_PITCH + tm4);
        uint32_t pb0 = pb[0], pb1 = pb[4];
        const uint32_t* pc = pb + 8 * PHI_PITCH;
        uint32_t pc0 = pc[0], pc1 = pc[4];

        float s0, s1, s2, s3, s4, s5, s6, s7;
        mma_tf32(s0, s1, s2, s3, ta0, ta1, ta2, ta3, pb0, pb1);
        mma_tf32(s4, s5, s6, s7, ta0, ta1, ta2, ta3, pc0, pc1);

        float e0 = ex2f(s0), e1 = ex2f(s1), e2 = ex2f(s2), e3 = ex2f(s3);
        float e4 = ex2f(s4), e5 = ex2f(s5), e6 = ex2f(s6), e7 = ex2f(s7);
        den_lo += (e0 + e1) + (e4 + e5);
        den_hi += (e2 + e3) + (e6 + e7);

        uint32_t pa0 = bf16pk(e1, e0);
        uint32_t pa1 = bf16pk(e3, e2);
        uint32_t pa2 = bf16pk(e5, e4);
        uint32_t pa3 = bf16pk(e7, e6);

        #pragma unroll
        for (int nt = 0; nt < 4; nt++) {
            const char* gb = g_s + (nt * 8 + t4) * G_PITCH_B + (m0 + 2 * tm4) * 2;
            uint32_t gb0 = *(const uint32_t*)gb;
            uint32_t gb1 = *(const uint32_t*)(gb + 16);
            mma_bf16(o + nt * 4, pa0, pa1, pa2, pa3, gb0, gb1);
        }
    }

    den_lo += __shfl_xor_sync(0xffffffffu, den_lo, 1);
    den_lo += __shfl_xor_sync(0xffffffffu, den_lo, 2);
    den_hi += __shfl_xor_sync(0xffffffffu, den_hi, 1);
    den_hi += __shfl_xor_sync(0xffffffffu, den_hi, 2);
    float il = 1.0f / den_lo;
    float ih = 1.0f / den_hi;

    // ---- fused output projection: O(bf16 A-frags) @ W_o^T + residual ----
    uint32_t pa[8];
    pa[0] = bf16pk(o[1] * il,  o[0] * il);     // rows t4,   ci 2tm4   (ci 0-7)
    pa[1] = bf16pk(o[3] * ih,  o[2] * ih);     // rows t4+8
    pa[2] = bf16pk(o[5] * il,  o[4] * il);     // rows t4,   ci 8+2tm4
    pa[3] = bf16pk(o[7] * ih,  o[6] * ih);
    pa[4] = bf16pk(o[9] * il,  o[8] * il);     // ci 16-23
    pa[5] = bf16pk(o[11] * ih, o[10] * ih);
    pa[6] = bf16pk(o[13] * il, o[12] * il);    // ci 24-31
    pa[7] = bf16pk(o[15] * ih, o[14] * ih);

    float gma = gam[0];
    const float* xb = x + (size_t)b * CC * NN;
    float* outb = out + (size_t)b * CC * NN;
    int q_lo = q0 + t4;
    int q_hi = q_lo + 8;

    #pragma unroll
    for (int ntc = 0; ntc < 8; ntc++) {
        const char* wb = wo_s + (ntc * 8 + t4) * 72 + tm4 * 4;
        uint32_t w0 = *(const uint32_t*)wb;
        uint32_t w1 = *(const uint32_t*)(wb + 16);
        uint32_t w2 = *(const uint32_t*)(wb + 32);
        uint32_t w3 = *(const uint32_t*)(wb + 48);
        float acc[4] = {0.0f, 0.0f, 0.0f, 0.0f};
        mma_bf16(acc, pa[0], pa[1], pa[2], pa[3], w0, w1);
        mma_bf16(acc, pa[4], pa[5], pa[6], pa[7], w2, w3);
        int c0 = ntc * 8 + 2 * tm4;
        size_t r0 = (size_t)c0 * NN, r1 = (size_t)(c0 + 1) * NN;
        outb[r0 + q_lo] = gma * (acc[0] + b_s[c0])     + xb[r0 + q_lo];
        outb[r1 + q_lo] = gma * (acc[1] + b_s[c0 + 1]) + xb[r1 + q_lo];
        outb[r0 + q_hi] = gma * (acc[2] + b_s[c0])     + xb[r0 + q_hi];
        outb[r1 + q_hi] = gma * (acc[3] + b_s[c0 + 1]) + xb[r1 + q_hi];
    }
}

// ---------------------------------------------------------------------------
extern "C" void kernel_launch(void* const* d_in, const int* in_sizes, int n_in,
                              void* d_out, int out_size) {
    const float* x   = (const float*)d_in[0];
    const float* Wt  = (const float*)d_in[1];
    const float* bt  = (const float*)d_in[2];
    const float* Wp  = (const float*)d_in[3];
    const float* bp  = (const float*)d_in[4];
    const float* Wg  = (const float*)d_in[5];
    const float* bg  = (const float*)d_in[6];
    const float* Wo  = (const float*)d_in[7];
    const float* bo  = (const float*)d_in[8];
    const float* gam = (const float*)d_in[9];
    float* out = (float*)d_out;

    pre_kernel<<<BB * MM * 4 / 256, 256>>>(x, Wt, bt, Wp, bp, Wg, bg);

    cudaFuncSetAttribute(attn_kernel,
                         cudaFuncAttributeMaxDynamicSharedMemorySize, SM_ATTN);
    attn_kernel<<<BB * 32, 256, SM_ATTN>>>(x, Wo, bo, gam, out);
}

// round 13
// speedup vs baseline: 3.8058x; 1.1749x over previous
#include <cuda_runtime.h>
#include <cuda_bf16.h>
#include <cstdint>

#define BB 16
#define CC 64
#define NN 4096   // H*W
#define MM 1024   // N/4

// Scratch (allocation-free: __device__ globals)
__device__ __align__(16) float g_theta[BB * NN * 8];              // [b][q][8]
__device__ __align__(16) float g_phi[BB * MM * 8];                // [b][m][8]
__device__ __align__(16) __nv_bfloat16 g_gbf[BB * 32 * MM];       // [b][c'][m] bf16

typedef unsigned long long ull;

__device__ __forceinline__ ull fma2(ull a, ull b, ull c) {
    ull d;
    asm("fma.rn.f32x2 %0, %1, %2, %3;" : "=l"(d) : "l"(a), "l"(b), "l"(c));
    return d;
}
__device__ __forceinline__ ull pack2(float lo, float hi) {
    ull d;
    asm("mov.b64 %0, {%1, %2};" : "=l"(d) : "f"(lo), "f"(hi));
    return d;
}
__device__ __forceinline__ void unpack2(ull v, float& lo, float& hi) {
    asm("mov.b64 {%0, %1}, %2;" : "=f"(lo), "=f"(hi) : "l"(v));
}
__device__ __forceinline__ uint32_t cvt_tf32(float f) {
    uint32_t r;
    asm("cvt.rna.tf32.f32 %0, %1;" : "=r"(r) : "f"(f));
    return r;
}
__device__ __forceinline__ float ex2f(float x) {
    float r;
    asm("ex2.approx.f32 %0, %1;" : "=f"(r) : "f"(x));
    return r;
}
// returns {lo, hi} packed bf16x2 (PTX: first operand -> high half)
__device__ __forceinline__ uint32_t bf16pk(float hi, float lo) {
    uint32_t r;
    asm("cvt.rn.bf16x2.f32 %0, %1, %2;" : "=r"(r) : "f"(hi), "f"(lo));
    return r;
}
__device__ __forceinline__ void mma_tf32(float& d0, float& d1, float& d2, float& d3,
        uint32_t a0, uint32_t a1, uint32_t a2, uint32_t a3,
        uint32_t b0, uint32_t b1) {
    asm("mma.sync.aligned.m16n8k8.row.col.f32.tf32.tf32.f32 "
        "{%0,%1,%2,%3}, {%4,%5,%6,%7}, {%8,%9}, {%10,%11,%12,%13};"
        : "=f"(d0), "=f"(d1), "=f"(d2), "=f"(d3)
        : "r"(a0), "r"(a1), "r"(a2), "r"(a3), "r"(b0), "r"(b1),
          "f"(0.0f), "f"(0.0f), "f"(0.0f), "f"(0.0f));
}
__device__ __forceinline__ void mma_bf16(float* d,
        uint32_t a0, uint32_t a1, uint32_t a2, uint32_t a3,
        uint32_t b0, uint32_t b1) {
    asm("mma.sync.aligned.m16n8k16.row.col.f32.bf16.bf16.f32 "
        "{%0,%1,%2,%3}, {%4,%5,%6,%7}, {%8,%9}, {%0,%1,%2,%3};"
        : "+f"(d[0]), "+f"(d[1]), "+f"(d[2]), "+f"(d[3])
        : "r"(a0), "r"(a1), "r"(a2), "r"(a3), "r"(b0), "r"(b1));
}

#define PHI_PITCH 10                    // floats per phi row (pad kills conflicts)
#define G_PITCH_B 2064                  // bytes per g row (1032 bf16): conflict-free
#define SM_PHI_B  (MM * PHI_PITCH * 4)  // 40960
#define SO_G      SM_PHI_B
#define SO_WO     (SO_G + 32 * G_PITCH_B)       // 107008; 64 rows x 72B
#define SO_BIAS   (SO_WO + 64 * 72)             // 111616; 64 floats
#define SM_ATTN   (SO_BIAS + 256)               // 111872

// ---------------------------------------------------------------------------
// Kernel 1: fused theta/phi/g. One thread per (pooled window, position).
// ---------------------------------------------------------------------------
__global__ void __launch_bounds__(256) pre_kernel(
        const float* __restrict__ x,
        const float* __restrict__ Wt, const float* __restrict__ bt,
        const float* __restrict__ Wp, const float* __restrict__ bp,
        const float* __restrict__ Wg, const float* __restrict__ bg) {
    __shared__ __align__(16) float WT[64 * 48];  // [c][o]: 0-7 th, 8-15 phi, 16-47 g
    __shared__ float b_s[48];
    int tid = threadIdx.x;
    for (int i = tid; i < 3072; i += 256) {
        int o = i % 48, c = i / 48;
        WT[i] = (o < 8) ? Wt[o * 64 + c]
              : (o < 16) ? Wp[(o - 8) * 64 + c]
                         : Wg[(o - 16) * 64 + c];
    }
    if (tid < 48) b_s[tid] = (tid < 8) ? bt[tid]
                           : (tid < 16) ? bp[tid - 8] : bg[tid - 16];
    __syncthreads();

    int idx = blockIdx.x * 256 + tid;
    int pm = idx >> 2;          // pooled pixel
    int pos = idx & 3;          // window position
    int b = pm >> 10;
    int m = pm & 1023;
    int hp = m >> 5, wp = m & 31;
    int q = (2 * hp + (pos >> 1)) * 64 + 2 * wp + (pos & 1);
    const float* xb = x + (size_t)b * CC * NN + q;

    ull y[24];
    #pragma unroll
    for (int j = 0; j < 24; j++) y[j] = 0ull;
    for (int c = 0; c < 64; c++) {
        float xv = xb[(size_t)c * NN];
        ull v2 = pack2(xv, xv);
        const ulonglong2* wr = (const ulonglong2*)(WT + c * 48);
        #pragma unroll
        for (int j = 0; j < 12; j++) {
            ulonglong2 wv = wr[j];
            y[2 * j]     = fma2(v2, wv.x, y[2 * j]);
            y[2 * j + 1] = fma2(v2, wv.y, y[2 * j + 1]);
        }
    }
    float v[48];
    #pragma unroll
    for (int j = 0; j < 24; j++) unpack2(y[j], v[2 * j], v[2 * j + 1]);

    // theta: every thread stores its own pixel
    {
        float4* op = (float4*)(g_theta + ((size_t)b * NN + q) * 8);
        op[0] = make_float4(v[0] + b_s[0], v[1] + b_s[1],
                            v[2] + b_s[2], v[3] + b_s[3]);
        op[1] = make_float4(v[4] + b_s[4], v[5] + b_s[5],
                            v[6] + b_s[6], v[7] + b_s[7]);
    }
    // phi/g: maxpool across the quad
    #pragma unroll
    for (int j = 8; j < 48; j++) {
        v[j] = fmaxf(v[j], __shfl_xor_sync(0xffffffffu, v[j], 1));
        v[j] = fmaxf(v[j], __shfl_xor_sync(0xffffffffu, v[j], 2));
    }
    if (pos == 0) {
        float* php = g_phi + (size_t)pm * 8;
        #pragma unroll
        for (int k = 0; k < 8; k++) php[k] = v[8 + k] + b_s[8 + k];
        __nv_bfloat16* gp = g_gbf + (size_t)b * 32 * MM + m;
        #pragma unroll
        for (int j = 0; j < 32; j++)
            gp[(size_t)j * MM] = __float2bfloat16(v[16 + j] + b_s[16 + j]);
    }
}

// ---------------------------------------------------------------------------
// Kernel 2: fused flash attention + output projection + residual.
//   Each warp handles TWO 16-query groups (q0.., q0+128..) against shared
//   key chunks: phi/g B-fragments are loaded once and reused by both A
//   fragments -> 2x arithmetic per LDS and 2x independent mma chains.
//   CTA covers 256 queries; grid = 256 = one full wave at 2 CTA/SM.
// ---------------------------------------------------------------------------
__global__ void __launch_bounds__(256, 2) attn_kernel(
        const float* __restrict__ x,
        const float* __restrict__ Wo, const float* __restrict__ bo,
        const float* __restrict__ gam,
        float* __restrict__ out) {
    extern __shared__ __align__(16) char sm[];
    float* phi_s = (float*)sm;                 // [1024][PHI_PITCH] tf32 bits
    char* g_s = sm + SO_G;                     // 32 rows x G_PITCH_B
    char* wo_s = sm + SO_WO;                   // 64 rows x 72B (bf16 pairs)
    float* b_s = (float*)(sm + SO_BIAS);       // 64 floats

    int tid = threadIdx.x;
    int b = blockIdx.x >> 4;
    int qt = blockIdx.x & 15;

    // Stage phi (tf32), g (bf16), W_o (bf16 pairs), bias
    {
        const float4* ps = (const float4*)(g_phi + (size_t)b * MM * 8);
        for (int i = tid; i < 2048; i += 256) {
            float4 t = ps[i];
            int m = i >> 1, h = (i & 1) * 4;
            uint32_t* dst = (uint32_t*)(phi_s + m * PHI_PITCH + h);
            dst[0] = cvt_tf32(t.x);
            dst[1] = cvt_tf32(t.y);
            dst[2] = cvt_tf32(t.z);
            dst[3] = cvt_tf32(t.w);
        }
        const uint4* gs = (const uint4*)(g_gbf + (size_t)b * 32 * MM);
        for (int i = tid; i < 4096; i += 256) {
            int row = i >> 7, col = i & 127;
            *(uint4*)(g_s + row * G_PITCH_B + col * 16) = gs[i];
        }
        for (int i = tid; i < 1024; i += 256) {        // W_o: [co][ci pair]
            int co = i >> 4, pr = i & 15;
            float lo = Wo[co * 32 + 2 * pr];
            float hi = Wo[co * 32 + 2 * pr + 1];
            *(uint32_t*)(wo_s + co * 72 + pr * 4) = bf16pk(hi, lo);
        }
        if (tid < 64) b_s[tid] = bo[tid];
    }
    __syncthreads();

    int w = tid >> 5, lane = tid & 31;
    int t4 = lane >> 2, tm4 = lane & 3;
    int q0 = qt * 256 + w * 16;            // group A queries
    int q1 = q0 + 128;                     // group B queries

    // theta A-fragments (tf32), pre-scaled by log2(e)
    const float L2E = 1.4426950408889634f;
    const float* tpA = g_theta + ((size_t)b * NN + q0) * 8;
    const float* tpB = g_theta + ((size_t)b * NN + q1) * 8;
    uint32_t taA0 = cvt_tf32(tpA[t4 * 8 + tm4] * L2E);
    uint32_t taA1 = cvt_tf32(tpA[(t4 + 8) * 8 + tm4] * L2E);
    uint32_t taA2 = cvt_tf32(tpA[t4 * 8 + tm4 + 4] * L2E);
    uint32_t taA3 = cvt_tf32(tpA[(t4 + 8) * 8 + tm4 + 4] * L2E);
    uint32_t taB0 = cvt_tf32(tpB[t4 * 8 + tm4] * L2E);
    uint32_t taB1 = cvt_tf32(tpB[(t4 + 8) * 8 + tm4] * L2E);
    uint32_t taB2 = cvt_tf32(tpB[t4 * 8 + tm4 + 4] * L2E);
    uint32_t taB3 = cvt_tf32(tpB[(t4 + 8) * 8 + tm4 + 4] * L2E);

    float oA[16], oB[16];
    #pragma unroll
    for (int j = 0; j < 16; j++) { oA[j] = 0.0f; oB[j] = 0.0f; }
    float denA_lo = 0.0f, denA_hi = 0.0f;
    float denB_lo = 0.0f, denB_hi = 0.0f;

    for (int ch = 0; ch < 64; ch++) {
        int m0 = ch * 16;
        // shared B-fragments (phi: two n8 key tiles)
        const uint32_t* pb = (const uint32_t*)(phi_s + (m0 + t4) * PHI_PITCH + tm4);
        uint32_t pb0 = pb[0], pb1 = pb[4];
        const uint32_t* pc = pb + 8 * PHI_PITCH;
        uint32_t pc0 = pc[0], pc1 = pc[4];
        // shared g B-fragments (4 channel tiles)
        uint32_t gb0[4], gb1[4];
        #pragma unroll
        for (int nt = 0; nt < 4; nt++) {
            const char* gb = g_s + (nt * 8 + t4) * G_PITCH_B + (m0 + 2 * tm4) * 2;
            gb0[nt] = *(const uint32_t*)gb;
            gb1[nt] = *(const uint32_t*)(gb + 16);
        }

        // ---- group A ----
        float s0, s1, s2, s3, s4, s5, s6, s7;
        mma_tf32(s0, s1, s2, s3, taA0, taA1, taA2, taA3, pb0, pb1);
        mma_tf32(s4, s5, s6, s7, taA0, taA1, taA2, taA3, pc0, pc1);
        float a0 = ex2f(s0), a1 = ex2f(s1), a2 = ex2f(s2), a3 = ex2f(s3);
        float a4 = ex2f(s4), a5 = ex2f(s5), a6 = ex2f(s6), a7 = ex2f(s7);
        denA_lo += (a0 + a1) + (a4 + a5);
        denA_hi += (a2 + a3) + (a6 + a7);
        uint32_t paA0 = bf16pk(a1, a0);
        uint32_t paA1 = bf16pk(a3, a2);
        uint32_t paA2 = bf16pk(a5, a4);
        uint32_t paA3 = bf16pk(a7, a6);

        // ---- group B ----
        float u0, u1, u2, u3, u4, u5, u6, u7;
        mma_tf32(u0, u1, u2, u3, taB0, taB1, taB2, taB3, pb0, pb1);
        mma_tf32(u4, u5, u6, u7, taB0, taB1, taB2, taB3, pc0, pc1);
        float c0 = ex2f(u0), c1 = ex2f(u1), c2 = ex2f(u2), c3 = ex2f(u3);
        float c4 = ex2f(u4), c5 = ex2f(u5), c6 = ex2f(u6), c7 = ex2f(u7);
        denB_lo += (c0 + c1) + (c4 + c5);
        denB_hi += (c2 + c3) + (c6 + c7);
        uint32_t paB0 = bf16pk(c1, c0);
        uint32_t paB1 = bf16pk(c3, c2);
        uint32_t paB2 = bf16pk(c5, c4);
        uint32_t paB3 = bf16pk(c7, c6);

        #pragma unroll
        for (int nt = 0; nt < 4; nt++) {
            mma_bf16(oA + nt * 4, paA0, paA1, paA2, paA3, gb0[nt], gb1[nt]);
            mma_bf16(oB + nt * 4, paB0, paB1, paB2, paB3, gb0[nt], gb1[nt]);
        }
    }

    denA_lo += __shfl_xor_sync(0xffffffffu, denA_lo, 1);
    denA_lo += __shfl_xor_sync(0xffffffffu, denA_lo, 2);
    denA_hi += __shfl_xor_sync(0xffffffffu, denA_hi, 1);
    denA_hi += __shfl_xor_sync(0xffffffffu, denA_hi, 2);
    denB_lo += __shfl_xor_sync(0xffffffffu, denB_lo, 1);
    denB_lo += __shfl_xor_sync(0xffffffffu, denB_lo, 2);
    denB_hi += __shfl_xor_sync(0xffffffffu, denB_hi, 1);
    denB_hi += __shfl_xor_sync(0xffffffffu, denB_hi, 2);
    float ilA = 1.0f / denA_lo, ihA = 1.0f / denA_hi;
    float ilB = 1.0f / denB_lo, ihB = 1.0f / denB_hi;

    // ---- fused output projection + residual, both groups ----
    uint32_t paA[8], paB[8];
    #pragma unroll
    for (int h = 0; h < 4; h++) {
        paA[2 * h]     = bf16pk(oA[4 * h + 1] * ilA, oA[4 * h]     * ilA);
        paA[2 * h + 1] = bf16pk(oA[4 * h + 3] * ihA, oA[4 * h + 2] * ihA);
        paB[2 * h]     = bf16pk(oB[4 * h + 1] * ilB, oB[4 * h]     * ilB);
        paB[2 * h + 1] = bf16pk(oB[4 * h + 3] * ihB, oB[4 * h + 2] * ihB);
    }

    float gma = gam[0];
    const float* xb = x + (size_t)b * CC * NN;
    float* outb = out + (size_t)b * CC * NN;
    int qA_lo = q0 + t4, qA_hi = qA_lo + 8;
    int qB_lo = q1 + t4, qB_hi = qB_lo + 8;

    #pragma unroll
    for (int ntc = 0; ntc < 8; ntc++) {
        const char* wb = wo_s + (ntc * 8 + t4) * 72 + tm4 * 4;
        uint32_t w0 = *(const uint32_t*)wb;
        uint32_t w1 = *(const uint32_t*)(wb + 16);
        uint32_t w2 = *(const uint32_t*)(wb + 32);
        uint32_t w3 = *(const uint32_t*)(wb + 48);
        int co = ntc * 8 + 2 * tm4;
        size_t r0 = (size_t)co * NN, r1 = (size_t)(co + 1) * NN;
        float bc0 = b_s[co], bc1 = b_s[co + 1];

        float accA[4] = {0.0f, 0.0f, 0.0f, 0.0f};
        mma_bf16(accA, paA[0], paA[1], paA[2], paA[3], w0, w1);
        mma_bf16(accA, paA[4], paA[5], paA[6], paA[7], w2, w3);
        outb[r0 + qA_lo] = gma * (accA[0] + bc0) + xb[r0 + qA_lo];
        outb[r1 + qA_lo] = gma * (accA[1] + bc1) + xb[r1 + qA_lo];
        outb[r0 + qA_hi] = gma * (accA[2] + bc0) + xb[r0 + qA_hi];
        outb[r1 + qA_hi] = gma * (accA[3] + bc1) + xb[r1 + qA_hi];

        float accB[4] = {0.0f, 0.0f, 0.0f, 0.0f};
        mma_bf16(accB, paB[0], paB[1], paB[2], paB[3], w0, w1);
        mma_bf16(accB, paB[4], paB[5], paB[6], paB[7], w2, w3);
        outb[r0 + qB_lo] = gma * (accB[0] + bc0) + xb[r0 + qB_lo];
        outb[r1 + qB_lo] = gma * (accB[1] + bc1) + xb[r1 + qB_lo];
        outb[r0 + qB_hi] = gma * (accB[2] + bc0) + xb[r0 + qB_hi];
        outb[r1 + qB_hi] = gma * (accB[3] + bc1) + xb[r1 + qB_hi];
    }
}

// ---------------------------------------------------------------------------
extern "C" void kernel_launch(void* const* d_in, const int* in_sizes, int n_in,
                              void* d_out, int out_size) {
    const float* x   = (const float*)d_in[0];
    const float* Wt  = (const float*)d_in[1];
    const float* bt  = (const float*)d_in[2];
    const float* Wp  = (const float*)d_in[3];
    const float* bp  = (const float*)d_in[4];
    const float* Wg  = (const float*)d_in[5];
    const float* bg  = (const float*)d_in[6];
    const float* Wo  = (const float*)d_in[7];
    const float* bo  = (const float*)d_in[8];
    const float* gam = (const float*)d_in[9];
    float* out = (float*)d_out;

    pre_kernel<<<BB * MM * 4 / 256, 256>>>(x, Wt, bt, Wp, bp, Wg, bg);

    cudaFuncSetAttribute(attn_kernel,
                         cudaFuncAttributeMaxDynamicSharedMemorySize, SM_ATTN);
    attn_kernel<<<BB * 16, 256, SM_ATTN>>>(x, Wo, bo, gam, out);
}

// round 14
// speedup vs baseline: 3.9455x; 1.0367x over previous
#include <cuda_runtime.h>
#include <cuda_bf16.h>
#include <cstdint>

#define BB 16
#define CC 64
#define NN 4096   // H*W
#define MM 1024   // N/4

// Scratch (allocation-free: __device__ globals)
__device__ __align__(16) float g_theta[BB * NN * 8];              // [b][q][8]
__device__ __align__(16) float g_phi[BB * MM * 8];                // [b][m][8]
__device__ __align__(16) __nv_bfloat16 g_gbf[BB * 32 * MM];       // [b][c'][m] bf16

typedef unsigned long long ull;

__device__ __forceinline__ ull fma2(ull a, ull b, ull c) {
    ull d;
    asm("fma.rn.f32x2 %0, %1, %2, %3;" : "=l"(d) : "l"(a), "l"(b), "l"(c));
    return d;
}
__device__ __forceinline__ ull pack2(float lo, float hi) {
    ull d;
    asm("mov.b64 %0, {%1, %2};" : "=l"(d) : "f"(lo), "f"(hi));
    return d;
}
__device__ __forceinline__ void unpack2(ull v, float& lo, float& hi) {
    asm("mov.b64 {%0, %1}, %2;" : "=f"(lo), "=f"(hi) : "l"(v));
}
__device__ __forceinline__ void u64lohi(ull v, uint32_t& lo, uint32_t& hi) {
    asm("mov.b64 {%0, %1}, %2;" : "=r"(lo), "=r"(hi) : "l"(v));
}
__device__ __forceinline__ uint32_t cvt_tf32(float f) {
    uint32_t r;
    asm("cvt.rna.tf32.f32 %0, %1;" : "=r"(r) : "f"(f));
    return r;
}
__device__ __forceinline__ float ex2f(float x) {
    float r;
    asm("ex2.approx.f32 %0, %1;" : "=f"(r) : "f"(x));
    return r;
}
// returns {lo, hi} packed bf16x2 (PTX: first operand -> high half)
__device__ __forceinline__ uint32_t bf16pk(float hi, float lo) {
    uint32_t r;
    asm("cvt.rn.bf16x2.f32 %0, %1, %2;" : "=r"(r) : "f"(hi), "f"(lo));
    return r;
}
__device__ __forceinline__ void mma_tf32(float& d0, float& d1, float& d2, float& d3,
        uint32_t a0, uint32_t a1, uint32_t a2, uint32_t a3,
        uint32_t b0, uint32_t b1) {
    asm("mma.sync.aligned.m16n8k8.row.col.f32.tf32.tf32.f32 "
        "{%0,%1,%2,%3}, {%4,%5,%6,%7}, {%8,%9}, {%10,%11,%12,%13};"
        : "=f"(d0), "=f"(d1), "=f"(d2), "=f"(d3)
        : "r"(a0), "r"(a1), "r"(a2), "r"(a3), "r"(b0), "r"(b1),
          "f"(0.0f), "f"(0.0f), "f"(0.0f), "f"(0.0f));
}
__device__ __forceinline__ void mma_bf16(float* d,
        uint32_t a0, uint32_t a1, uint32_t a2, uint32_t a3,
        uint32_t b0, uint32_t b1) {
    asm("mma.sync.aligned.m16n8k16.row.col.f32.bf16.bf16.f32 "
        "{%0,%1,%2,%3}, {%4,%5,%6,%7}, {%8,%9}, {%0,%1,%2,%3};"
        : "+f"(d[0]), "+f"(d[1]), "+f"(d[2]), "+f"(d[3])
        : "r"(a0), "r"(a1), "r"(a2), "r"(a3), "r"(b0), "r"(b1));
}

// SMEM layout (attn):
//   phi_p: [1024 rows][32B]  row m, slot t (0-3): u64 {tf32 phi[m][t], tf32 phi[m][t+4]}
//   g_p:   [32 rows][2080B]  row r, chunk c, slot t: u64 {bf16x2(g[r][16c+2t..]),
//                                                         bf16x2(g[r][16c+2t+8..])}
//          pitch 2080 ≡ 32 (mod 128) -> conflict-free LDS.64 phases
#define SO_G      32768
#define G_PITCH   2080
#define G_NT      (8 * G_PITCH)                 // 16640: 8 rows per channel tile
#define SO_WO     (SO_G + 32 * G_PITCH)         // 99328; 64 rows x 72B
#define SO_BIAS   (SO_WO + 64 * 72)             // 103936; 64 floats
#define SM_ATTN   (SO_BIAS + 256)               // 104192

// ---------------------------------------------------------------------------
// Kernel 1: fused theta/phi/g. One thread per (pooled window, position).
// ---------------------------------------------------------------------------
__global__ void __launch_bounds__(256) pre_kernel(
        const float* __restrict__ x,
        const float* __restrict__ Wt, const float* __restrict__ bt,
        const float* __restrict__ Wp, const float* __restrict__ bp,
        const float* __restrict__ Wg, const float* __restrict__ bg) {
    __shared__ __align__(16) float WT[64 * 48];  // [c][o]: 0-7 th, 8-15 phi, 16-47 g
    __shared__ float b_s[48];
    int tid = threadIdx.x;
    for (int i = tid; i < 3072; i += 256) {
        int o = i % 48, c = i / 48;
        WT[i] = (o < 8) ? Wt[o * 64 + c]
              : (o < 16) ? Wp[(o - 8) * 64 + c]
                         : Wg[(o - 16) * 64 + c];
    }
    if (tid < 48) b_s[tid] = (tid < 8) ? bt[tid]
                           : (tid < 16) ? bp[tid - 8] : bg[tid - 16];
    __syncthreads();

    int idx = blockIdx.x * 256 + tid;
    int pm = idx >> 2;          // pooled pixel
    int pos = idx & 3;          // window position
    int b = pm >> 10;
    int m = pm & 1023;
    int hp = m >> 5, wp = m & 31;
    int q = (2 * hp + (pos >> 1)) * 64 + 2 * wp + (pos & 1);
    const float* xb = x + (size_t)b * CC * NN + q;

    ull y[24];
    #pragma unroll
    for (int j = 0; j < 24; j++) y[j] = 0ull;
    #pragma unroll 4
    for (int c = 0; c < 64; c++) {
        float xv = xb[(size_t)c * NN];
        ull v2 = pack2(xv, xv);
        const ulonglong2* wr = (const ulonglong2*)(WT + c * 48);
        #pragma unroll
        for (int j = 0; j < 12; j++) {
            ulonglong2 wv = wr[j];
            y[2 * j]     = fma2(v2, wv.x, y[2 * j]);
            y[2 * j + 1] = fma2(v2, wv.y, y[2 * j + 1]);
        }
    }
    float v[48];
    #pragma unroll
    for (int j = 0; j < 24; j++) unpack2(y[j], v[2 * j], v[2 * j + 1]);

    // theta: every thread stores its own pixel
    {
        float4* op = (float4*)(g_theta + ((size_t)b * NN + q) * 8);
        op[0] = make_float4(v[0] + b_s[0], v[1] + b_s[1],
                            v[2] + b_s[2], v[3] + b_s[3]);
        op[1] = make_float4(v[4] + b_s[4], v[5] + b_s[5],
                            v[6] + b_s[6], v[7] + b_s[7]);
    }
    // phi/g: maxpool across the quad
    #pragma unroll
    for (int j = 8; j < 48; j++) {
        v[j] = fmaxf(v[j], __shfl_xor_sync(0xffffffffu, v[j], 1));
        v[j] = fmaxf(v[j], __shfl_xor_sync(0xffffffffu, v[j], 2));
    }
    if (pos == 0) {
        float* php = g_phi + (size_t)pm * 8;
        #pragma unroll
        for (int k = 0; k < 8; k++) php[k] = v[8 + k] + b_s[8 + k];
        __nv_bfloat16* gp = g_gbf + (size_t)b * 32 * MM + m;
        #pragma unroll
        for (int j = 0; j < 32; j++)
            gp[(size_t)j * MM] = __float2bfloat16(v[16 + j] + b_s[16 + j]);
    }
}

// ---------------------------------------------------------------------------
// Kernel 2: fused flash attention + output projection + residual.
//   Two 16-query groups per warp share key-chunk B fragments; smem operands
//   packed so every B fragment is one LDS.64 and chunk advance is two
//   pointer increments.
// ---------------------------------------------------------------------------
__global__ void __launch_bounds__(256, 2) attn_kernel(
        const float* __restrict__ x,
        const float* __restrict__ Wo, const float* __restrict__ bo,
        const float* __restrict__ gam,
        float* __restrict__ out) {
    extern __shared__ __align__(16) char sm[];
    char* wo_s = sm + SO_WO;                   // 64 rows x 72B (bf16 pairs)
    float* b_s = (float*)(sm + SO_BIAS);       // 64 floats

    int tid = threadIdx.x;
    int b = blockIdx.x >> 4;
    int qt = blockIdx.x & 15;

    // Stage phi (packed tf32 pairs), g (packed bf16 u64 slots), W_o, bias
    {
        for (int m = tid; m < 1024; m += 256) {
            const float4* pr = (const float4*)(g_phi + ((size_t)b * MM + m) * 8);
            float4 f0 = pr[0], f1 = pr[1];
            uint2* dst = (uint2*)(sm + m * 32);
            dst[0] = make_uint2(cvt_tf32(f0.x), cvt_tf32(f1.x));
            dst[1] = make_uint2(cvt_tf32(f0.y), cvt_tf32(f1.y));
            dst[2] = make_uint2(cvt_tf32(f0.z), cvt_tf32(f1.z));
            dst[3] = make_uint2(cvt_tf32(f0.w), cvt_tf32(f1.w));
        }
        const uint32_t* gsrc = (const uint32_t*)(g_gbf + (size_t)b * 32 * MM);
        for (int i = tid; i < 8192; i += 256) {
            int r = i >> 8;            // 0..31
            int c = (i >> 2) & 63;     // chunk
            int t = i & 3;             // slot
            const uint32_t* src = gsrc + r * (MM / 2) + c * 8;
            *(uint2*)(sm + SO_G + r * G_PITCH + c * 32 + t * 8) =
                make_uint2(src[t], src[t + 4]);
        }
        for (int i = tid; i < 1024; i += 256) {        // W_o: [co][ci pair]
            int co = i >> 4, pr = i & 15;
            float lo = Wo[co * 32 + 2 * pr];
            float hi = Wo[co * 32 + 2 * pr + 1];
            *(uint32_t*)(wo_s + co * 72 + pr * 4) = bf16pk(hi, lo);
        }
        if (tid < 64) b_s[tid] = bo[tid];
    }
    __syncthreads();

    int w = tid >> 5, lane = tid & 31;
    int t4 = lane >> 2, tm4 = lane & 3;
    int q0 = qt * 256 + w * 16;            // group A queries
    int q1 = q0 + 128;                     // group B queries

    // theta A-fragments (tf32), pre-scaled by log2(e)
    const float L2E = 1.4426950408889634f;
    const float* tpA = g_theta + ((size_t)b * NN + q0) * 8;
    const float* tpB = g_theta + ((size_t)b * NN + q1) * 8;
    uint32_t taA0 = cvt_tf32(tpA[t4 * 8 + tm4] * L2E);
    uint32_t taA1 = cvt_tf32(tpA[(t4 + 8) * 8 + tm4] * L2E);
    uint32_t taA2 = cvt_tf32(tpA[t4 * 8 + tm4 + 4] * L2E);
    uint32_t taA3 = cvt_tf32(tpA[(t4 + 8) * 8 + tm4 + 4] * L2E);
    uint32_t taB0 = cvt_tf32(tpB[t4 * 8 + tm4] * L2E);
    uint32_t taB1 = cvt_tf32(tpB[(t4 + 8) * 8 + tm4] * L2E);
    uint32_t taB2 = cvt_tf32(tpB[t4 * 8 + tm4 + 4] * L2E);
    uint32_t taB3 = cvt_tf32(tpB[(t4 + 8) * 8 + tm4 + 4] * L2E);

    float oA[16], oB[16];
    #pragma unroll
    for (int j = 0; j < 16; j++) { oA[j] = 0.0f; oB[j] = 0.0f; }
    float denA_lo = 0.0f, denA_hi = 0.0f;
    float denB_lo = 0.0f, denB_hi = 0.0f;

    const char* pp = sm + t4 * 32 + tm4 * 8;                 // phi ptr, +512/chunk
    const char* gp = sm + SO_G + t4 * G_PITCH + tm4 * 8;     // g ptr,  +32/chunk

    #pragma unroll 2
    for (int ch = 0; ch < 64; ch++) {
        // B fragments: 6x LDS.64, zero address math
        ull vpb = *(const ull*)pp;
        ull vpc = *(const ull*)(pp + 256);
        ull vg0 = *(const ull*)gp;
        ull vg1 = *(const ull*)(gp + G_NT);
        ull vg2 = *(const ull*)(gp + 2 * G_NT);
        ull vg3 = *(const ull*)(gp + 3 * G_NT);
        pp += 512;
        gp += 32;

        uint32_t pb0, pb1, pc0, pc1;
        u64lohi(vpb, pb0, pb1);
        u64lohi(vpc, pc0, pc1);
        uint32_t gb0[4], gb1[4];
        u64lohi(vg0, gb0[0], gb1[0]);
        u64lohi(vg1, gb0[1], gb1[1]);
        u64lohi(vg2, gb0[2], gb1[2]);
        u64lohi(vg3, gb0[3], gb1[3]);

        // ---- group A ----
        float s0, s1, s2, s3, s4, s5, s6, s7;
        mma_tf32(s0, s1, s2, s3, taA0, taA1, taA2, taA3, pb0, pb1);
        mma_tf32(s4, s5, s6, s7, taA0, taA1, taA2, taA3, pc0, pc1);
        float a0 = ex2f(s0), a1 = ex2f(s1), a2 = ex2f(s2), a3 = ex2f(s3);
        float a4 = ex2f(s4), a5 = ex2f(s5), a6 = ex2f(s6), a7 = ex2f(s7);
        denA_lo += (a0 + a1) + (a4 + a5);
        denA_hi += (a2 + a3) + (a6 + a7);
        uint32_t paA0 = bf16pk(a1, a0);
        uint32_t paA1 = bf16pk(a3, a2);
        uint32_t paA2 = bf16pk(a5, a4);
        uint32_t paA3 = bf16pk(a7, a6);

        // ---- group B ----
        float u0, u1, u2, u3, u4, u5, u6, u7;
        mma_tf32(u0, u1, u2, u3, taB0, taB1, taB2, taB3, pb0, pb1);
        mma_tf32(u4, u5, u6, u7, taB0, taB1, taB2, taB3, pc0, pc1);
        float c0 = ex2f(u0), c1 = ex2f(u1), c2 = ex2f(u2), c3 = ex2f(u3);
        float c4 = ex2f(u4), c5 = ex2f(u5), c6 = ex2f(u6), c7 = ex2f(u7);
        denB_lo += (c0 + c1) + (c4 + c5);
        denB_hi += (c2 + c3) + (c6 + c7);
        uint32_t paB0 = bf16pk(c1, c0);
        uint32_t paB1 = bf16pk(c3, c2);
        uint32_t paB2 = bf16pk(c5, c4);
        uint32_t paB3 = bf16pk(c7, c6);

        #pragma unroll
        for (int nt = 0; nt < 4; nt++) {
            mma_bf16(oA + nt * 4, paA0, paA1, paA2, paA3, gb0[nt], gb1[nt]);
            mma_bf16(oB + nt * 4, paB0, paB1, paB2, paB3, gb0[nt], gb1[nt]);
        }
    }

    denA_lo += __shfl_xor_sync(0xffffffffu, denA_lo, 1);
    denA_lo += __shfl_xor_sync(0xffffffffu, denA_lo, 2);
    denA_hi += __shfl_xor_sync(0xffffffffu, denA_hi, 1);
    denA_hi += __shfl_xor_sync(0xffffffffu, denA_hi, 2);
    denB_lo += __shfl_xor_sync(0xffffffffu, denB_lo, 1);
    denB_lo += __shfl_xor_sync(0xffffffffu, denB_lo, 2);
    denB_hi += __shfl_xor_sync(0xffffffffu, denB_hi, 1);
    denB_hi += __shfl_xor_sync(0xffffffffu, denB_hi, 2);
    float ilA = 1.0f / denA_lo, ihA = 1.0f / denA_hi;
    float ilB = 1.0f / denB_lo, ihB = 1.0f / denB_hi;

    // ---- fused output projection + residual, both groups ----
    uint32_t paA[8], paB[8];
    #pragma unroll
    for (int h = 0; h < 4; h++) {
        paA[2 * h]     = bf16pk(oA[4 * h + 1] * ilA, oA[4 * h]     * ilA);
        paA[2 * h + 1] = bf16pk(oA[4 * h + 3] * ihA, oA[4 * h + 2] * ihA);
        paB[2 * h]     = bf16pk(oB[4 * h + 1] * ilB, oB[4 * h]     * ilB);
        paB[2 * h + 1] = bf16pk(oB[4 * h + 3] * ihB, oB[4 * h + 2] * ihB);
    }

    float gma = gam[0];
    const float* xb = x + (size_t)b * CC * NN;
    float* outb = out + (size_t)b * CC * NN;
    int qA_lo = q0 + t4, qA_hi = qA_lo + 8;
    int qB_lo = q1 + t4, qB_hi = qB_lo + 8;

    #pragma unroll
    for (int ntc = 0; ntc < 8; ntc++) {
        const char* wb = wo_s + (ntc * 8 + t4) * 72 + tm4 * 4;
        uint32_t w0 = *(const uint32_t*)wb;
        uint32_t w1 = *(const uint32_t*)(wb + 16);
        uint32_t w2 = *(const uint32_t*)(wb + 32);
        uint32_t w3 = *(const uint32_t*)(wb + 48);
        int co = ntc * 8 + 2 * tm4;
        size_t r0 = (size_t)co * NN, r1 = (size_t)(co + 1) * NN;
        float bc0 = b_s[co], bc1 = b_s[co + 1];

        float accA[4] = {0.0f, 0.0f, 0.0f, 0.0f};
        mma_bf16(accA, paA[0], paA[1], paA[2], paA[3], w0, w1);
        mma_bf16(accA, paA[4], paA[5], paA[6], paA[7], w2, w3);
        outb[r0 + qA_lo] = gma * (accA[0] + bc0) + xb[r0 + qA_lo];
        outb[r1 + qA_lo] = gma * (accA[1] + bc1) + xb[r1 + qA_lo];
        outb[r0 + qA_hi] = gma * (accA[2] + bc0) + xb[r0 + qA_hi];
        outb[r1 + qA_hi] = gma * (accA[3] + bc1) + xb[r1 + qA_hi];

        float accB[4] = {0.0f, 0.0f, 0.0f, 0.0f};
        mma_bf16(accB, paB[0], paB[1], paB[2], paB[3], w0, w1);
        mma_bf16(accB, paB[4], paB[5], paB[6], paB[7], w2, w3);
        outb[r0 + qB_lo] = gma * (accB[0] + bc0) + xb[r0 + qB_lo];
        outb[r1 + qB_lo] = gma * (accB[1] + bc1) + xb[r1 + qB_lo];
        outb[r0 + qB_hi] = gma * (accB[2] + bc0) + xb[r0 + qB_hi];
        outb[r1 + qB_hi] = gma * (accB[3] + bc1) + xb[r1 + qB_hi];
    }
}

// ---------------------------------------------------------------------------
extern "C" void kernel_launch(void* const* d_in, const int* in_sizes, int n_in,
                              void* d_out, int out_size) {
    const float* x   = (const float*)d_in[0];
    const float* Wt  = (const float*)d_in[1];
    const float* bt  = (const float*)d_in[2];
    const float* Wp  = (const float*)d_in[3];
    const float* bp  = (const float*)d_in[4];
    const float* Wg  = (const float*)d_in[5];
    const float* bg  = (const float*)d_in[6];
    const float* Wo  = (const float*)d_in[7];
    const float* bo  = (const float*)d_in[8];
    const float* gam = (const float*)d_in[9];
    float* out = (float*)d_out;

    pre_kernel<<<BB * MM * 4 / 256, 256>>>(x, Wt, bt, Wp, bp, Wg, bg);

    cudaFuncSetAttribute(attn_kernel,
                         cudaFuncAttributeMaxDynamicSharedMemorySize, SM_ATTN);
    attn_kernel<<<BB * 16, 256, SM_ATTN>>>(x, Wo, bo, gam, out);
}